// round 10
// baseline (speedup 1.0000x reference)
#include <cuda_runtime.h>
#include <cuda_fp16.h>
#include <cstdint>

#define N_NODES 55296
#define N_EDGES 221184
#define NROWS   (2 * N_NODES)   /* B*N = 110592 */
#define EPC     256             /* edges per CTA */
#define NTILES  (N_EDGES / EPC) /* 864 */

// ---------------- scratch (device globals; no allocation) ----------------
__device__ float  d_g [(size_t)N_EDGES * 32];     // relu(edge MLP hidden)
__device__ float  d_h [(size_t)NROWS * 32];       // hidden/node carry
__device__ float  d_agg[(size_t)NROWS * 32];      // scatter accumulator
__device__ __half d_BT[32 * 1056];                // BT[o][k*32+h]=ew2[k,h*32+o]; BT[o][1024+h]=eb2[h*32+o]

__device__ __forceinline__ float sigm(float x) {
    return __fdividef(1.f, 1.f + __expf(-x));
}
__device__ __forceinline__ float fast_tanh(float x) {
    float t = __expf(2.f * x);
    return 1.f - __fdividef(2.f, t + 1.f);
}

// smem layout for msg kernel (bytes), EPC=256
#define BSTRIDE 1064     /* halves; 532 words = 20 mod 32 -> conflict-free */
#define XSTRIDE 40       /* halves; 20 words mod 32 -> conflict-free */
#define SM_B    0        /* 32 rows x 1064 halves = 68096 */
#define SM_X    68096    /* 2*256 rows x 40 halves = 40960 */
#define SM_G    109056   /* 256 rows x 40 halves = 20480 */
#define SM_SRC  129536   /* 1024 */
#define SM_DST  130560   /* 1024 */
#define SM_TOTAL 131584

// ---------------- h0: project node features + zero agg ----------------
__global__ void h0_kernel(const float* __restrict__ x,
                          const float* __restrict__ pw1, const float* __restrict__ pb1,
                          const float* __restrict__ pw2, const float* __restrict__ pb2) {
    __shared__ float w1s[1024], w2s[1024], b1s[32], b2s[32];
    int tid = threadIdx.x;
    for (int idx = tid; idx < 1024; idx += 256) { w1s[idx] = pw1[idx]; w2s[idx] = pw2[idx]; }
    if (tid < 32) { b1s[tid] = pb1[tid]; b2s[tid] = pb2[tid]; }
    __syncthreads();
    int row = blockIdx.x * 8 + (tid >> 5);
    int j = tid & 31;
    float xj = x[(size_t)row * 32 + j];
    float a = b1s[j];
#pragma unroll
    for (int i = 0; i < 32; i++) a = fmaf(__shfl_sync(0xffffffffu, xj, i), w1s[i * 32 + j], a);
    a = fmaxf(a, 0.f);
    float o = b2s[j];
#pragma unroll
    for (int i = 0; i < 32; i++) o = fmaf(__shfl_sync(0xffffffffu, a, i), w2s[i * 32 + j], o);
    d_h[(size_t)row * 32 + j] = o;
    d_agg[(size_t)row * 32 + j] = 0.f;
}

// ---------------- prep: g = relu(er@ew1+eb1)  AND  BT transpose (merged) ----------------
#define G_BLOCKS 27648   /* (N_EDGES*32)/256 */
__global__ void prep_kernel(const float* __restrict__ er,
                            const float* __restrict__ ew1, const float* __restrict__ eb1,
                            const float* __restrict__ ew2, const float* __restrict__ eb2) {
    int bid = blockIdx.x;
    if (bid < G_BLOCKS) {
        int tid = bid * 256 + threadIdx.x;
        int e = tid >> 5, j = tid & 31;
        float4 rv = __ldg((const float4*)er + e);
        float a = __ldg(eb1 + j);
        a = fmaf(rv.x, __ldg(ew1 + j),      a);
        a = fmaf(rv.y, __ldg(ew1 + 32 + j), a);
        a = fmaf(rv.z, __ldg(ew1 + 64 + j), a);
        a = fmaf(rv.w, __ldg(ew1 + 96 + j), a);
        d_g[tid] = fmaxf(a, 0.f);
    } else {
        int t = (bid - G_BLOCKS) * 256 + threadIdx.x;
        if (t >= 32 * 1056) return;
        int o = t / 1056, K = t % 1056;
        float v;
        if (K < 1024) {
            int k = K >> 5, h = K & 31;
            v = ew2[k * 1024 + h * 32 + o];
        } else {
            v = eb2[(K - 1024) * 32 + o];
        }
        d_BT[t] = __float2half_rn(v);
    }
}

// ---------------- mma.sync helper ----------------
__device__ __forceinline__ void mma_f16(float& d0, float& d1, float& d2, float& d3,
                                        uint32_t a0, uint32_t a1, uint32_t a2, uint32_t a3,
                                        uint32_t b0, uint32_t b1) {
    asm volatile("mma.sync.aligned.m16n8k16.row.col.f32.f16.f16.f32 "
                 "{%0,%1,%2,%3}, {%4,%5,%6,%7}, {%8,%9}, {%0,%1,%2,%3};"
                 : "+f"(d0), "+f"(d1), "+f"(d2), "+f"(d3)
                 : "r"(a0), "r"(a1), "r"(a2), "r"(a3), "r"(b0), "r"(b1));
}

// ---------------- fused msg: D = (g ox x) @ W2^T via mma.sync, red-scatter ----------------
__global__ void __launch_bounds__(256, 1) msg_fused(const int* __restrict__ esrc,
                                                    const int* __restrict__ edst) {
    extern __shared__ char smem[];
    __half* Bs = (__half*)(smem + SM_B);
    __half* xs = (__half*)(smem + SM_X);
    __half* gs = (__half*)(smem + SM_G);
    int* srcs = (int*)(smem + SM_SRC);
    int* dsts = (int*)(smem + SM_DST);

    int tid = threadIdx.x;
    int w = tid >> 5, l = tid & 31;
    int e0 = blockIdx.x * EPC;

    { srcs[tid] = esrc[e0 + tid]; dsts[tid] = edst[e0 + tid]; }
    __syncthreads();

    for (int idx = tid; idx < 4224; idx += 256) {
        int o = idx / 132, c8 = (idx - o * 132) * 8;
        *(uint4*)(Bs + o * BSTRIDE + c8) = ((const uint4*)d_BT)[idx];
    }
#pragma unroll
    for (int it = 0; it < 8; it++) {
        int t = tid + it * 256;
        int b = t >> 10, rq = t & 1023;
        int row = rq >> 2, qq = rq & 3;
        int src = srcs[row];
        const float4* p = (const float4*)(d_h + ((size_t)b * N_NODES + src) * 32 + qq * 8);
        float4 v0 = p[0], v1 = p[1];
        __half2 h0 = __floats2half2_rn(v0.x, v0.y), h1 = __floats2half2_rn(v0.z, v0.w);
        __half2 h2 = __floats2half2_rn(v1.x, v1.y), h3 = __floats2half2_rn(v1.z, v1.w);
        uint4 pk = { *(uint32_t*)&h0, *(uint32_t*)&h1, *(uint32_t*)&h2, *(uint32_t*)&h3 };
        *(uint4*)(xs + (b * 256 + row) * XSTRIDE + qq * 8) = pk;
    }
#pragma unroll
    for (int it = 0; it < 4; it++) {
        int t = tid + it * 256;
        int row = t >> 2, qq = t & 3;
        const float4* p = (const float4*)(d_g + (size_t)(e0 + row) * 32 + qq * 8);
        float4 v0 = p[0], v1 = p[1];
        __half2 h0 = __floats2half2_rn(v0.x, v0.y), h1 = __floats2half2_rn(v0.z, v0.w);
        __half2 h2 = __floats2half2_rn(v1.x, v1.y), h3 = __floats2half2_rn(v1.z, v1.w);
        uint4 pk = { *(uint32_t*)&h0, *(uint32_t*)&h1, *(uint32_t*)&h2, *(uint32_t*)&h3 };
        *(uint4*)(gs + row * XSTRIDE + qq * 8) = pk;
    }
    __syncthreads();

    int q = l & 3, r0 = l >> 2, q2 = q * 2;
    int rowbase = w * 32;
    int row4[4] = { rowbase + r0, rowbase + r0 + 8, rowbase + r0 + 16, rowbase + r0 + 24 };

    uint32_t xr[2][4][4];
#pragma unroll
    for (int b = 0; b < 2; b++)
#pragma unroll
        for (int i = 0; i < 4; i++) {
            const __half* xp = xs + (b * 256 + row4[i]) * XSTRIDE + q2;
#pragma unroll
            for (int p = 0; p < 4; p++) xr[b][i][p] = *(const uint32_t*)(xp + 8 * p);
        }

    float acc[2][2][4][4];
#pragma unroll
    for (int b = 0; b < 2; b++)
#pragma unroll
        for (int mt = 0; mt < 2; mt++)
#pragma unroll
            for (int nt = 0; nt < 4; nt++)
#pragma unroll
                for (int d = 0; d < 4; d++) acc[b][mt][nt][d] = 0.f;

    for (int kk = 0; kk < 33; kk++) {
        bool hasg = (kk < 32);
        __half2 g2[4];
        if (hasg) {
#pragma unroll
            for (int i = 0; i < 4; i++) g2[i] = __half2half2(gs[row4[i] * XSTRIDE + kk]);
        }
#pragma unroll
        for (int hh = 0; hh < 2; hh++) {
            int Kb = kk * 32 + hh * 16;
            uint32_t bf[4][2];
#pragma unroll
            for (int nt = 0; nt < 4; nt++) {
                const __half* bp = Bs + (nt * 8 + r0) * BSTRIDE + Kb + q2;
                bf[nt][0] = *(const uint32_t*)bp;
                bf[nt][1] = *(const uint32_t*)(bp + 8);
            }
#pragma unroll
            for (int b = 0; b < 2; b++) {
#pragma unroll
                for (int mt = 0; mt < 2; mt++) {
                    uint32_t a0 = xr[b][2 * mt][2 * hh],     a1 = xr[b][2 * mt + 1][2 * hh];
                    uint32_t a2 = xr[b][2 * mt][2 * hh + 1], a3 = xr[b][2 * mt + 1][2 * hh + 1];
                    if (hasg) {
                        __half2 gA = g2[2 * mt], gB = g2[2 * mt + 1];
                        __half2 t;
                        t = __hmul2(gA, *(__half2*)&a0); a0 = *(uint32_t*)&t;
                        t = __hmul2(gB, *(__half2*)&a1); a1 = *(uint32_t*)&t;
                        t = __hmul2(gA, *(__half2*)&a2); a2 = *(uint32_t*)&t;
                        t = __hmul2(gB, *(__half2*)&a3); a3 = *(uint32_t*)&t;
                    }
#pragma unroll
                    for (int nt = 0; nt < 4; nt++)
                        mma_f16(acc[b][mt][nt][0], acc[b][mt][nt][1], acc[b][mt][nt][2], acc[b][mt][nt][3],
                                a0, a1, a2, a3, bf[nt][0], bf[nt][1]);
                }
            }
        }
    }
#pragma unroll
    for (int b = 0; b < 2; b++)
#pragma unroll
        for (int mt = 0; mt < 2; mt++) {
            int dA = dsts[row4[2 * mt]], dB = dsts[row4[2 * mt + 1]];
            float* pA = d_agg + ((size_t)b * N_NODES + dA) * 32 + q2;
            float* pB = d_agg + ((size_t)b * N_NODES + dB) * 32 + q2;
#pragma unroll
            for (int nt = 0; nt < 4; nt++) {
                asm volatile("red.global.add.v2.f32 [%0], {%1,%2};"
                             :: "l"(pA + nt * 8), "f"(acc[b][mt][nt][0]), "f"(acc[b][mt][nt][1]) : "memory");
                asm volatile("red.global.add.v2.f32 [%0], {%1,%2};"
                             :: "l"(pB + nt * 8), "f"(acc[b][mt][nt][2]), "f"(acc[b][mt][nt][3]) : "memory");
            }
        }
}

// ---------------- GRU step via mma.sync: 64 rows/CTA, 4 warps (re-zeroes agg) ----------------
// Weight rows permuted so each 8-col group jt holds its (r,z,n) triplet:
//   phys = jt*24 + gate*8 + rr   for logical n = gate*32 + jt*8 + rr
#define GHS 34   /* hf32 stride (floats) */
__global__ void __launch_bounds__(128, 6) gru_kernel(
                           const float* __restrict__ conv_b,
                           const float* __restrict__ wih, const float* __restrict__ whh,
                           const float* __restrict__ bih, const float* __restrict__ bhh,
                           float* __restrict__ out, int last) {
    __shared__ __half Bih[96 * 40], Bhh[96 * 40];   // [phys][k], stride 40 halves
    __shared__ __half x16[64 * 40], h16[64 * 40];   // [row][k]
    __shared__ float  hf[64 * GHS];                 // fp32 carry
    __shared__ float  bihs[96], bhhs[96], cbs[32];
    int tid = threadIdx.x;

    if (tid < 96) { bihs[tid] = bih[tid]; bhhs[tid] = bhh[tid]; }
    if (tid < 32) cbs[tid] = conv_b[tid];
    __syncthreads();   // cbs ready for staging

    // stage weights (permuted, fp16)
    for (int idx = tid; idx < 6144; idx += 128) {
        int ih = (idx < 3072);
        int t = ih ? idx : idx - 3072;
        int n = t >> 5, k = t & 31;
        int gate = n >> 5, j = n & 31;
        int phys = (j >> 3) * 24 + gate * 8 + (j & 7);
        __half v = __float2half_rn(ih ? wih[t] : whh[t]);
        (ih ? Bih : Bhh)[phys * 40 + k] = v;
    }
    // stage x = relu(agg + cb), h (fp16 + fp32), re-zero agg
    int row0 = blockIdx.x * 64;
#pragma unroll
    for (int it = 0; it < 16; it++) {
        int idx = tid + it * 128;
        int rr = idx >> 5, c = idx & 31;
        size_t off = (size_t)(row0 + rr) * 32 + c;
        float hv = d_h[off];
        float xv = fmaxf(d_agg[off] + cbs[c], 0.f);
        d_agg[off] = 0.f;
        x16[rr * 40 + c] = __float2half_rn(xv);
        h16[rr * 40 + c] = __float2half_rn(hv);
        hf[rr * GHS + c] = hv;
    }
    __syncthreads();

    int w = tid >> 5, l = tid & 31;
    int q = l & 3, r0 = l >> 2, q2 = q * 2;
    int wrow = w * 16;
    float* dst = last ? out : (float*)d_h;

    // A fragments: rows wrow+r0 (lo) and wrow+r0+8 (hi), k = q2 + 8p
    uint32_t ax0[4], ax1[4], ah0[4], ah1[4];
    {
        const __half* xpl = x16 + (wrow + r0) * 40 + q2;
        const __half* xph = x16 + (wrow + r0 + 8) * 40 + q2;
        const __half* hpl = h16 + (wrow + r0) * 40 + q2;
        const __half* hph = h16 + (wrow + r0 + 8) * 40 + q2;
#pragma unroll
        for (int p = 0; p < 4; p++) {
            ax0[p] = *(const uint32_t*)(xpl + 8 * p);
            ax1[p] = *(const uint32_t*)(xph + 8 * p);
            ah0[p] = *(const uint32_t*)(hpl + 8 * p);
            ah1[p] = *(const uint32_t*)(hph + 8 * p);
        }
    }

#pragma unroll
    for (int jt = 0; jt < 4; jt++) {
        float ax[3][4], ah[3][4];
#pragma unroll
        for (int g = 0; g < 3; g++)
#pragma unroll
            for (int d = 0; d < 4; d++) { ax[g][d] = 0.f; ah[g][d] = 0.f; }
#pragma unroll
        for (int g = 0; g < 3; g++) {
            int phys = jt * 24 + g * 8 + r0;
            const __half* bi = Bih + phys * 40 + q2;
            const __half* bh = Bhh + phys * 40 + q2;
            uint32_t bi0 = *(const uint32_t*)bi,        bi1 = *(const uint32_t*)(bi + 8);
            uint32_t bi2 = *(const uint32_t*)(bi + 16), bi3 = *(const uint32_t*)(bi + 24);
            uint32_t bh0 = *(const uint32_t*)bh,        bh1 = *(const uint32_t*)(bh + 8);
            uint32_t bh2 = *(const uint32_t*)(bh + 16), bh3 = *(const uint32_t*)(bh + 24);
            mma_f16(ax[g][0], ax[g][1], ax[g][2], ax[g][3], ax0[0], ax1[0], ax0[1], ax1[1], bi0, bi1);
            mma_f16(ax[g][0], ax[g][1], ax[g][2], ax[g][3], ax0[2], ax1[2], ax0[3], ax1[3], bi2, bi3);
            mma_f16(ah[g][0], ah[g][1], ah[g][2], ah[g][3], ah0[0], ah1[0], ah0[1], ah1[1], bh0, bh1);
            mma_f16(ah[g][0], ah[g][1], ah[g][2], ah[g][3], ah0[2], ah1[2], ah0[3], ah1[3], bh2, bh3);
        }
        int colb = jt * 8 + q2;
        float bir0 = bihs[colb] + bhhs[colb],           bir1 = bihs[colb + 1] + bhhs[colb + 1];
        float biz0 = bihs[32 + colb] + bhhs[32 + colb], biz1 = bihs[33 + colb] + bhhs[33 + colb];
        float bxn0 = bihs[64 + colb], bxn1 = bihs[65 + colb];
        float bhn0 = bhhs[64 + colb], bhn1 = bhhs[65 + colb];
#pragma unroll
        for (int half = 0; half < 2; half++) {          // half 0: d0,d1 (row r0); half 1: d2,d3 (row r0+8)
            int row = wrow + r0 + half * 8;
            int d0 = half * 2, d1 = half * 2 + 1;
            float2 hv = *(const float2*)&hf[row * GHS + colb];
            float rg0 = sigm(ax[0][d0] + ah[0][d0] + bir0);
            float zg0 = sigm(ax[1][d0] + ah[1][d0] + biz0);
            float ng0 = fast_tanh(ax[2][d0] + bxn0 + rg0 * (ah[2][d0] + bhn0));
            float rg1 = sigm(ax[0][d1] + ah[0][d1] + bir1);
            float zg1 = sigm(ax[1][d1] + ah[1][d1] + biz1);
            float ng1 = fast_tanh(ax[2][d1] + bxn1 + rg1 * (ah[2][d1] + bhn1));
            float2 o;
            o.x = (1.f - zg0) * ng0 + zg0 * hv.x;
            o.y = (1.f - zg1) * ng1 + zg1 * hv.y;
            *(float2*)&dst[(size_t)(row0 + row) * 32 + colb] = o;
        }
    }
}

// ---------------- launch ----------------
extern "C" void kernel_launch(void* const* d_in, const int* in_sizes, int n_in,
                              void* d_out, int out_size) {
    const float* x     = (const float*)d_in[0];
    const float* er    = (const float*)d_in[1];
    const float* pw1   = (const float*)d_in[2];
    const float* pb1   = (const float*)d_in[3];
    const float* pw2   = (const float*)d_in[4];
    const float* pb2   = (const float*)d_in[5];
    const float* ew1   = (const float*)d_in[6];
    const float* eb1   = (const float*)d_in[7];
    const float* ew2   = (const float*)d_in[8];
    const float* eb2   = (const float*)d_in[9];
    const float* convb = (const float*)d_in[10];
    const float* wih   = (const float*)d_in[11];
    const float* whh   = (const float*)d_in[12];
    const float* bih   = (const float*)d_in[13];
    const float* bhh   = (const float*)d_in[14];
    const int*   esrc  = (const int*)d_in[15];
    const int*   edst  = (const int*)d_in[16];
    float* outp = (float*)d_out;

    cudaFuncSetAttribute(msg_fused, cudaFuncAttributeMaxDynamicSharedMemorySize, SM_TOTAL);

    h0_kernel<<<NROWS / 8, 256>>>(x, pw1, pb1, pw2, pb2);
    prep_kernel<<<G_BLOCKS + 132, 256>>>(er, ew1, eb1, ew2, eb2);
    for (int s = 0; s < 3; s++) {
        msg_fused<<<NTILES, 256, SM_TOTAL>>>(esrc, edst);
        gru_kernel<<<NROWS / 64, 128>>>(convb, wih, whh, bih, bhh, outp, s == 2 ? 1 : 0);
    }
}

// round 11
// speedup vs baseline: 1.2741x; 1.2741x over previous
#include <cuda_runtime.h>
#include <cuda_fp16.h>
#include <cstdint>

#define N_NODES 55296
#define N_EDGES 221184
#define NROWS   (2 * N_NODES)   /* B*N = 110592 */
#define EPC     256             /* edges per CTA */
#define NTILES  (N_EDGES / EPC) /* 864 */

// ---------------- scratch (device globals; no allocation) ----------------
__device__ float  d_g [(size_t)N_EDGES * 32];     // relu(edge MLP hidden)
__device__ float  d_h [(size_t)NROWS * 32];       // hidden/node carry
__device__ float  d_agg[(size_t)NROWS * 32];      // scatter accumulator
__device__ __half d_BT[32 * 1056];                // BT[o][k*32+h]=ew2[k,h*32+o]; BT[o][1024+h]=eb2[h*32+o]
__device__ __half d_Wp[7680];                     // permuted GRU weights: [0,3840)=Wih, [3840,7680)=Whh, rows of 40

__device__ __forceinline__ float sigm(float x) {
    return __fdividef(1.f, 1.f + __expf(-x));
}
__device__ __forceinline__ float fast_tanh(float x) {
    float t = __expf(2.f * x);
    return 1.f - __fdividef(2.f, t + 1.f);
}

// smem layout for msg kernel (bytes), EPC=256
#define BSTRIDE 1064     /* halves; 532 words = 20 mod 32 -> conflict-free */
#define XSTRIDE 40       /* halves; 20 words mod 32 -> conflict-free */
#define SM_B    0        /* 32 rows x 1064 halves = 68096 */
#define SM_X    68096    /* 2*256 rows x 40 halves = 40960 */
#define SM_G    109056   /* 256 rows x 40 halves = 20480 */
#define SM_SRC  129536   /* 1024 */
#define SM_DST  130560   /* 1024 */
#define SM_TOTAL 131584

// smem layout for gru kernel (bytes), 128 rows/CTA
#define GHS     34       /* hf stride (floats) */
#define GW_OFF  0        /* 7680 halves = 15360 B (Wih @0, Whh @3840 halves) */
#define GX_OFF  15360    /* 128*40 halves = 10240 B */
#define GH_OFF  25600    /* 128*40 halves = 10240 B */
#define GF_OFF  35840    /* 128*34 floats = 17408 B */
#define GBI_OFF 53248    /* 96 floats */
#define GBH_OFF 53632    /* 96 floats */
#define GCB_OFF 54016    /* 32 floats */
#define G_TOTAL 54144

// ---------------- h0: project node features + zero agg ----------------
__global__ void h0_kernel(const float* __restrict__ x,
                          const float* __restrict__ pw1, const float* __restrict__ pb1,
                          const float* __restrict__ pw2, const float* __restrict__ pb2) {
    __shared__ float w1s[1024], w2s[1024], b1s[32], b2s[32];
    int tid = threadIdx.x;
    for (int idx = tid; idx < 1024; idx += 256) { w1s[idx] = pw1[idx]; w2s[idx] = pw2[idx]; }
    if (tid < 32) { b1s[tid] = pb1[tid]; b2s[tid] = pb2[tid]; }
    __syncthreads();
    int row = blockIdx.x * 8 + (tid >> 5);
    int j = tid & 31;
    float xj = x[(size_t)row * 32 + j];
    float a = b1s[j];
#pragma unroll
    for (int i = 0; i < 32; i++) a = fmaf(__shfl_sync(0xffffffffu, xj, i), w1s[i * 32 + j], a);
    a = fmaxf(a, 0.f);
    float o = b2s[j];
#pragma unroll
    for (int i = 0; i < 32; i++) o = fmaf(__shfl_sync(0xffffffffu, a, i), w2s[i * 32 + j], o);
    d_h[(size_t)row * 32 + j] = o;
    d_agg[(size_t)row * 32 + j] = 0.f;
}

// ---------------- prep: g, BT transpose, GRU weight permute (merged) ----------------
#define G_BLOCKS 27648   /* (N_EDGES*32)/256 */
#define BT_BLOCKS 132
#define WP_BLOCKS 24     /* 6144/256 */
__global__ void prep_kernel(const float* __restrict__ er,
                            const float* __restrict__ ew1, const float* __restrict__ eb1,
                            const float* __restrict__ ew2, const float* __restrict__ eb2,
                            const float* __restrict__ wih, const float* __restrict__ whh) {
    int bid = blockIdx.x;
    if (bid < G_BLOCKS) {
        int tid = bid * 256 + threadIdx.x;
        int e = tid >> 5, j = tid & 31;
        float4 rv = __ldg((const float4*)er + e);
        float a = __ldg(eb1 + j);
        a = fmaf(rv.x, __ldg(ew1 + j),      a);
        a = fmaf(rv.y, __ldg(ew1 + 32 + j), a);
        a = fmaf(rv.z, __ldg(ew1 + 64 + j), a);
        a = fmaf(rv.w, __ldg(ew1 + 96 + j), a);
        d_g[tid] = fmaxf(a, 0.f);
    } else if (bid < G_BLOCKS + BT_BLOCKS) {
        int t = (bid - G_BLOCKS) * 256 + threadIdx.x;
        if (t >= 32 * 1056) return;
        int o = t / 1056, K = t % 1056;
        float v;
        if (K < 1024) {
            int k = K >> 5, h = K & 31;
            v = ew2[k * 1024 + h * 32 + o];
        } else {
            v = eb2[(K - 1024) * 32 + o];
        }
        d_BT[t] = __float2half_rn(v);
    } else {
        // GRU weight permute: phys = (j>>3)*24 + gate*8 + (j&7) for logical n=gate*32+j
        int t = (bid - G_BLOCKS - BT_BLOCKS) * 256 + threadIdx.x;   // 0..6143
        if (t >= 6144) return;
        int ih = (t < 3072);
        int tt = ih ? t : t - 3072;
        int n = tt >> 5, k = tt & 31;
        int gate = n >> 5, j = n & 31;
        int phys = (j >> 3) * 24 + gate * 8 + (j & 7);
        d_Wp[(ih ? 0 : 3840) + phys * 40 + k] = __float2half_rn(ih ? wih[tt] : whh[tt]);
    }
}

// ---------------- mma.sync helper ----------------
__device__ __forceinline__ void mma_f16(float& d0, float& d1, float& d2, float& d3,
                                        uint32_t a0, uint32_t a1, uint32_t a2, uint32_t a3,
                                        uint32_t b0, uint32_t b1) {
    asm volatile("mma.sync.aligned.m16n8k16.row.col.f32.f16.f16.f32 "
                 "{%0,%1,%2,%3}, {%4,%5,%6,%7}, {%8,%9}, {%0,%1,%2,%3};"
                 : "+f"(d0), "+f"(d1), "+f"(d2), "+f"(d3)
                 : "r"(a0), "r"(a1), "r"(a2), "r"(a3), "r"(b0), "r"(b1));
}

// ---------------- fused msg: D = (g ox x) @ W2^T via mma.sync, red-scatter ----------------
__global__ void __launch_bounds__(256, 1) msg_fused(const int* __restrict__ esrc,
                                                    const int* __restrict__ edst) {
    extern __shared__ char smem[];
    __half* Bs = (__half*)(smem + SM_B);
    __half* xs = (__half*)(smem + SM_X);
    __half* gs = (__half*)(smem + SM_G);
    int* srcs = (int*)(smem + SM_SRC);
    int* dsts = (int*)(smem + SM_DST);

    int tid = threadIdx.x;
    int w = tid >> 5, l = tid & 31;
    int e0 = blockIdx.x * EPC;

    { srcs[tid] = esrc[e0 + tid]; dsts[tid] = edst[e0 + tid]; }
    __syncthreads();

    for (int idx = tid; idx < 4224; idx += 256) {
        int o = idx / 132, c8 = (idx - o * 132) * 8;
        *(uint4*)(Bs + o * BSTRIDE + c8) = ((const uint4*)d_BT)[idx];
    }
#pragma unroll
    for (int it = 0; it < 8; it++) {
        int t = tid + it * 256;
        int b = t >> 10, rq = t & 1023;
        int row = rq >> 2, qq = rq & 3;
        int src = srcs[row];
        const float4* p = (const float4*)(d_h + ((size_t)b * N_NODES + src) * 32 + qq * 8);
        float4 v0 = p[0], v1 = p[1];
        __half2 h0 = __floats2half2_rn(v0.x, v0.y), h1 = __floats2half2_rn(v0.z, v0.w);
        __half2 h2 = __floats2half2_rn(v1.x, v1.y), h3 = __floats2half2_rn(v1.z, v1.w);
        uint4 pk = { *(uint32_t*)&h0, *(uint32_t*)&h1, *(uint32_t*)&h2, *(uint32_t*)&h3 };
        *(uint4*)(xs + (b * 256 + row) * XSTRIDE + qq * 8) = pk;
    }
#pragma unroll
    for (int it = 0; it < 4; it++) {
        int t = tid + it * 256;
        int row = t >> 2, qq = t & 3;
        const float4* p = (const float4*)(d_g + (size_t)(e0 + row) * 32 + qq * 8);
        float4 v0 = p[0], v1 = p[1];
        __half2 h0 = __floats2half2_rn(v0.x, v0.y), h1 = __floats2half2_rn(v0.z, v0.w);
        __half2 h2 = __floats2half2_rn(v1.x, v1.y), h3 = __floats2half2_rn(v1.z, v1.w);
        uint4 pk = { *(uint32_t*)&h0, *(uint32_t*)&h1, *(uint32_t*)&h2, *(uint32_t*)&h3 };
        *(uint4*)(gs + row * XSTRIDE + qq * 8) = pk;
    }
    __syncthreads();

    int q = l & 3, r0 = l >> 2, q2 = q * 2;
    int rowbase = w * 32;
    int row4[4] = { rowbase + r0, rowbase + r0 + 8, rowbase + r0 + 16, rowbase + r0 + 24 };

    uint32_t xr[2][4][4];
#pragma unroll
    for (int b = 0; b < 2; b++)
#pragma unroll
        for (int i = 0; i < 4; i++) {
            const __half* xp = xs + (b * 256 + row4[i]) * XSTRIDE + q2;
#pragma unroll
            for (int p = 0; p < 4; p++) xr[b][i][p] = *(const uint32_t*)(xp + 8 * p);
        }

    float acc[2][2][4][4];
#pragma unroll
    for (int b = 0; b < 2; b++)
#pragma unroll
        for (int mt = 0; mt < 2; mt++)
#pragma unroll
            for (int nt = 0; nt < 4; nt++)
#pragma unroll
                for (int d = 0; d < 4; d++) acc[b][mt][nt][d] = 0.f;

    for (int kk = 0; kk < 33; kk++) {
        bool hasg = (kk < 32);
        __half2 g2[4];
        if (hasg) {
#pragma unroll
            for (int i = 0; i < 4; i++) g2[i] = __half2half2(gs[row4[i] * XSTRIDE + kk]);
        }
#pragma unroll
        for (int hh = 0; hh < 2; hh++) {
            int Kb = kk * 32 + hh * 16;
            uint32_t bf[4][2];
#pragma unroll
            for (int nt = 0; nt < 4; nt++) {
                const __half* bp = Bs + (nt * 8 + r0) * BSTRIDE + Kb + q2;
                bf[nt][0] = *(const uint32_t*)bp;
                bf[nt][1] = *(const uint32_t*)(bp + 8);
            }
#pragma unroll
            for (int b = 0; b < 2; b++) {
#pragma unroll
                for (int mt = 0; mt < 2; mt++) {
                    uint32_t a0 = xr[b][2 * mt][2 * hh],     a1 = xr[b][2 * mt + 1][2 * hh];
                    uint32_t a2 = xr[b][2 * mt][2 * hh + 1], a3 = xr[b][2 * mt + 1][2 * hh + 1];
                    if (hasg) {
                        __half2 gA = g2[2 * mt], gB = g2[2 * mt + 1];
                        __half2 t;
                        t = __hmul2(gA, *(__half2*)&a0); a0 = *(uint32_t*)&t;
                        t = __hmul2(gB, *(__half2*)&a1); a1 = *(uint32_t*)&t;
                        t = __hmul2(gA, *(__half2*)&a2); a2 = *(uint32_t*)&t;
                        t = __hmul2(gB, *(__half2*)&a3); a3 = *(uint32_t*)&t;
                    }
#pragma unroll
                    for (int nt = 0; nt < 4; nt++)
                        mma_f16(acc[b][mt][nt][0], acc[b][mt][nt][1], acc[b][mt][nt][2], acc[b][mt][nt][3],
                                a0, a1, a2, a3, bf[nt][0], bf[nt][1]);
                }
            }
        }
    }
#pragma unroll
    for (int b = 0; b < 2; b++)
#pragma unroll
        for (int mt = 0; mt < 2; mt++) {
            int dA = dsts[row4[2 * mt]], dB = dsts[row4[2 * mt + 1]];
            float* pA = d_agg + ((size_t)b * N_NODES + dA) * 32 + q2;
            float* pB = d_agg + ((size_t)b * N_NODES + dB) * 32 + q2;
#pragma unroll
            for (int nt = 0; nt < 4; nt++) {
                asm volatile("red.global.add.v2.f32 [%0], {%1,%2};"
                             :: "l"(pA + nt * 8), "f"(acc[b][mt][nt][0]), "f"(acc[b][mt][nt][1]) : "memory");
                asm volatile("red.global.add.v2.f32 [%0], {%1,%2};"
                             :: "l"(pB + nt * 8), "f"(acc[b][mt][nt][2]), "f"(acc[b][mt][nt][3]) : "memory");
            }
        }
}

// ---------------- GRU via mma.sync: 128 rows/CTA, 8 warps, precomputed weights ----------------
__global__ void __launch_bounds__(256, 3) gru_kernel(
                           const float* __restrict__ conv_b,
                           const float* __restrict__ bih, const float* __restrict__ bhh,
                           float* __restrict__ out, int last) {
    extern __shared__ char gsm[];
    __half* Bih = (__half*)(gsm + GW_OFF);
    __half* Bhh = Bih + 3840;
    __half* x16 = (__half*)(gsm + GX_OFF);
    __half* h16 = (__half*)(gsm + GH_OFF);
    float*  hf  = (float*)(gsm + GF_OFF);
    float*  bihs = (float*)(gsm + GBI_OFF);
    float*  bhhs = (float*)(gsm + GBH_OFF);
    float*  cbs  = (float*)(gsm + GCB_OFF);
    int tid = threadIdx.x;

    if (tid < 96) { bihs[tid] = bih[tid]; bhhs[tid] = bhh[tid]; }
    if (tid < 32) cbs[tid] = conv_b[tid];
    // straight copy of permuted weights: 960 uint4
    {
        const uint4* wsrc = (const uint4*)d_Wp;
        uint4* wdst = (uint4*)(gsm + GW_OFF);
#pragma unroll
        for (int it = 0; it < 4; it++) {
            int idx = tid + it * 256;
            if (idx < 960) wdst[idx] = wsrc[idx];
        }
    }
    __syncthreads();   // cbs ready

    // stage x/h vectorized: 1024 tasks (128 rows x 8 quads)
    int row0 = blockIdx.x * 128;
#pragma unroll
    for (int it = 0; it < 4; it++) {
        int t = tid + it * 256;
        int rr = t >> 3, qq = t & 7;
        size_t off = (size_t)(row0 + rr) * 32 + qq * 4;
        float4 hv = *(const float4*)(d_h + off);
        float4 av = *(const float4*)(d_agg + off);
        *(float4*)(d_agg + off) = make_float4(0.f, 0.f, 0.f, 0.f);
        float4 cb4 = *(const float4*)&cbs[qq * 4];
        float x0 = fmaxf(av.x + cb4.x, 0.f), x1 = fmaxf(av.y + cb4.y, 0.f);
        float x2 = fmaxf(av.z + cb4.z, 0.f), x3 = fmaxf(av.w + cb4.w, 0.f);
        __half2 xa = __floats2half2_rn(x0, x1), xb = __floats2half2_rn(x2, x3);
        __half2 ha = __floats2half2_rn(hv.x, hv.y), hb = __floats2half2_rn(hv.z, hv.w);
        uint2 xpk = { *(uint32_t*)&xa, *(uint32_t*)&xb };
        uint2 hpk = { *(uint32_t*)&ha, *(uint32_t*)&hb };
        *(uint2*)(x16 + rr * 40 + qq * 4) = xpk;
        *(uint2*)(h16 + rr * 40 + qq * 4) = hpk;
        *(float2*)&hf[rr * GHS + qq * 4] = make_float2(hv.x, hv.y);
        *(float2*)&hf[rr * GHS + qq * 4 + 2] = make_float2(hv.z, hv.w);
    }
    __syncthreads();

    int w = tid >> 5, l = tid & 31;
    int q = l & 3, r0 = l >> 2, q2 = q * 2;
    int wrow = w * 16;
    float* dst = last ? out : (float*)d_h;

    uint32_t ax0[4], ax1[4], ah0[4], ah1[4];
    {
        const __half* xpl = x16 + (wrow + r0) * 40 + q2;
        const __half* xph = x16 + (wrow + r0 + 8) * 40 + q2;
        const __half* hpl = h16 + (wrow + r0) * 40 + q2;
        const __half* hph = h16 + (wrow + r0 + 8) * 40 + q2;
#pragma unroll
        for (int p = 0; p < 4; p++) {
            ax0[p] = *(const uint32_t*)(xpl + 8 * p);
            ax1[p] = *(const uint32_t*)(xph + 8 * p);
            ah0[p] = *(const uint32_t*)(hpl + 8 * p);
            ah1[p] = *(const uint32_t*)(hph + 8 * p);
        }
    }

#pragma unroll
    for (int jt = 0; jt < 4; jt++) {
        float ax[3][4], ah[3][4];
#pragma unroll
        for (int g = 0; g < 3; g++)
#pragma unroll
            for (int d = 0; d < 4; d++) { ax[g][d] = 0.f; ah[g][d] = 0.f; }
#pragma unroll
        for (int g = 0; g < 3; g++) {
            int phys = jt * 24 + g * 8 + r0;
            const __half* bi = Bih + phys * 40 + q2;
            const __half* bh = Bhh + phys * 40 + q2;
            uint32_t bi0 = *(const uint32_t*)bi,        bi1 = *(const uint32_t*)(bi + 8);
            uint32_t bi2 = *(const uint32_t*)(bi + 16), bi3 = *(const uint32_t*)(bi + 24);
            uint32_t bh0 = *(const uint32_t*)bh,        bh1 = *(const uint32_t*)(bh + 8);
            uint32_t bh2 = *(const uint32_t*)(bh + 16), bh3 = *(const uint32_t*)(bh + 24);
            mma_f16(ax[g][0], ax[g][1], ax[g][2], ax[g][3], ax0[0], ax1[0], ax0[1], ax1[1], bi0, bi1);
            mma_f16(ax[g][0], ax[g][1], ax[g][2], ax[g][3], ax0[2], ax1[2], ax0[3], ax1[3], bi2, bi3);
            mma_f16(ah[g][0], ah[g][1], ah[g][2], ah[g][3], ah0[0], ah1[0], ah0[1], ah1[1], bh0, bh1);
            mma_f16(ah[g][0], ah[g][1], ah[g][2], ah[g][3], ah0[2], ah1[2], ah0[3], ah1[3], bh2, bh3);
        }
        int colb = jt * 8 + q2;
        float bir0 = bihs[colb] + bhhs[colb],           bir1 = bihs[colb + 1] + bhhs[colb + 1];
        float biz0 = bihs[32 + colb] + bhhs[32 + colb], biz1 = bihs[33 + colb] + bhhs[33 + colb];
        float bxn0 = bihs[64 + colb], bxn1 = bihs[65 + colb];
        float bhn0 = bhhs[64 + colb], bhn1 = bhhs[65 + colb];
#pragma unroll
        for (int half = 0; half < 2; half++) {
            int row = wrow + r0 + half * 8;
            int d0 = half * 2, d1 = half * 2 + 1;
            float2 hv = *(const float2*)&hf[row * GHS + colb];
            float rg0 = sigm(ax[0][d0] + ah[0][d0] + bir0);
            float zg0 = sigm(ax[1][d0] + ah[1][d0] + biz0);
            float ng0 = fast_tanh(ax[2][d0] + bxn0 + rg0 * (ah[2][d0] + bhn0));
            float rg1 = sigm(ax[0][d1] + ah[0][d1] + bir1);
            float zg1 = sigm(ax[1][d1] + ah[1][d1] + biz1);
            float ng1 = fast_tanh(ax[2][d1] + bxn1 + rg1 * (ah[2][d1] + bhn1));
            float2 o;
            o.x = (1.f - zg0) * ng0 + zg0 * hv.x;
            o.y = (1.f - zg1) * ng1 + zg1 * hv.y;
            *(float2*)&dst[(size_t)(row0 + row) * 32 + colb] = o;
        }
    }
}

// ---------------- launch ----------------
extern "C" void kernel_launch(void* const* d_in, const int* in_sizes, int n_in,
                              void* d_out, int out_size) {
    const float* x     = (const float*)d_in[0];
    const float* er    = (const float*)d_in[1];
    const float* pw1   = (const float*)d_in[2];
    const float* pb1   = (const float*)d_in[3];
    const float* pw2   = (const float*)d_in[4];
    const float* pb2   = (const float*)d_in[5];
    const float* ew1   = (const float*)d_in[6];
    const float* eb1   = (const float*)d_in[7];
    const float* ew2   = (const float*)d_in[8];
    const float* eb2   = (const float*)d_in[9];
    const float* convb = (const float*)d_in[10];
    const float* wih   = (const float*)d_in[11];
    const float* whh   = (const float*)d_in[12];
    const float* bih   = (const float*)d_in[13];
    const float* bhh   = (const float*)d_in[14];
    const int*   esrc  = (const int*)d_in[15];
    const int*   edst  = (const int*)d_in[16];
    float* outp = (float*)d_out;

    cudaFuncSetAttribute(msg_fused, cudaFuncAttributeMaxDynamicSharedMemorySize, SM_TOTAL);
    cudaFuncSetAttribute(gru_kernel, cudaFuncAttributeMaxDynamicSharedMemorySize, G_TOTAL);

    h0_kernel<<<NROWS / 8, 256>>>(x, pw1, pb1, pw2, pb2);
    prep_kernel<<<G_BLOCKS + BT_BLOCKS + WP_BLOCKS, 256>>>(er, ew1, eb1, ew2, eb2, wih, whh);
    for (int s = 0; s < 3; s++) {
        msg_fused<<<NTILES, 256, SM_TOTAL>>>(esrc, edst);
        gru_kernel<<<NROWS / 128, 256, G_TOTAL>>>(convb, bih, bhh, outp, s == 2 ? 1 : 0);
    }
}

// round 12
// speedup vs baseline: 1.5379x; 1.2070x over previous
#include <cuda_runtime.h>
#include <cuda_fp16.h>
#include <cstdint>

#define N_NODES 55296
#define N_EDGES 221184
#define NROWS   (2 * N_NODES)   /* B*N = 110592 */
#define EPC     512             /* edges per CTA */
#define NTILES  (N_EDGES / EPC) /* 432 */

// ---------------- scratch (device globals; no allocation) ----------------
__device__ float  d_g [(size_t)N_EDGES * 32];     // relu(edge MLP hidden)
__device__ float  d_h [(size_t)NROWS * 32];       // hidden/node carry
__device__ float  d_agg[(size_t)NROWS * 32];      // scatter accumulator
__device__ __half d_BT[32 * 1056];                // BT[o][k*32+h]=ew2[k,h*32+o]; BT[o][1024+h]=eb2[h*32+o]
__device__ __half d_Wp[7680];                     // permuted GRU weights: [0,3840)=Wih, [3840,7680)=Whh, rows of 40

__device__ __forceinline__ float sigm(float x) {
    return __fdividef(1.f, 1.f + __expf(-x));
}
__device__ __forceinline__ float fast_tanh(float x) {
    float t = __expf(2.f * x);
    return 1.f - __fdividef(2.f, t + 1.f);
}

// smem layout for msg kernel (bytes), EPC=512
#define BSTRIDE 1064     /* halves; 532 words = 20 mod 32 -> conflict-free */
#define XSTRIDE 40       /* halves; 20 words mod 32 -> conflict-free */
#define SM_B    0        /* 32 rows x 1064 halves = 68096 */
#define SM_X    68096    /* 2*512 rows x 40 halves = 81920 */
#define SM_G    150016   /* 512 rows x 40 halves = 40960 */
#define SM_SRC  190976   /* 2048 */
#define SM_DST  193024   /* 2048 */
#define SM_TOTAL 195072

// smem layout for gru kernel (bytes), 128 rows/CTA
#define GHS     34       /* hf stride (floats) */
#define GW_OFF  0        /* 7680 halves = 15360 B (Wih @0, Whh @3840 halves) */
#define GX_OFF  15360    /* 128*40 halves = 10240 B */
#define GH_OFF  25600    /* 128*40 halves = 10240 B */
#define GF_OFF  35840    /* 128*34 floats = 17408 B */
#define GBI_OFF 53248    /* 96 floats */
#define GBH_OFF 53632    /* 96 floats */
#define GCB_OFF 54016    /* 32 floats */
#define G_TOTAL 54144

// ---------------- prep: g, BT transpose, GRU weight permute, h0 projection (merged) ----------------
#define G_BLOCKS 27648   /* (N_EDGES*32)/256 */
#define BT_BLOCKS 132
#define WP_BLOCKS 24     /* 6144/256 */
#define H0_BLOCKS (NROWS / 8)  /* 13824 */
__global__ void prep_kernel(const float* __restrict__ er,
                            const float* __restrict__ ew1, const float* __restrict__ eb1,
                            const float* __restrict__ ew2, const float* __restrict__ eb2,
                            const float* __restrict__ wih, const float* __restrict__ whh,
                            const float* __restrict__ x,
                            const float* __restrict__ pw1, const float* __restrict__ pb1,
                            const float* __restrict__ pw2, const float* __restrict__ pb2) {
    __shared__ float w1s[1024], w2s[1024], b1s[32], b2s[32];
    int bid = blockIdx.x;
    if (bid < G_BLOCKS) {
        int tid = bid * 256 + threadIdx.x;
        int e = tid >> 5, j = tid & 31;
        float4 rv = __ldg((const float4*)er + e);
        float a = __ldg(eb1 + j);
        a = fmaf(rv.x, __ldg(ew1 + j),      a);
        a = fmaf(rv.y, __ldg(ew1 + 32 + j), a);
        a = fmaf(rv.z, __ldg(ew1 + 64 + j), a);
        a = fmaf(rv.w, __ldg(ew1 + 96 + j), a);
        d_g[tid] = fmaxf(a, 0.f);
    } else if (bid < G_BLOCKS + BT_BLOCKS) {
        int t = (bid - G_BLOCKS) * 256 + threadIdx.x;
        if (t >= 32 * 1056) return;
        int o = t / 1056, K = t % 1056;
        float v;
        if (K < 1024) {
            int k = K >> 5, h = K & 31;
            v = ew2[k * 1024 + h * 32 + o];
        } else {
            v = eb2[(K - 1024) * 32 + o];
        }
        d_BT[t] = __float2half_rn(v);
    } else if (bid < G_BLOCKS + BT_BLOCKS + WP_BLOCKS) {
        // GRU weight permute: phys = (j>>3)*24 + gate*8 + (j&7) for logical n=gate*32+j
        int t = (bid - G_BLOCKS - BT_BLOCKS) * 256 + threadIdx.x;   // 0..6143
        if (t >= 6144) return;
        int ih = (t < 3072);
        int tt = ih ? t : t - 3072;
        int n = tt >> 5, k = tt & 31;
        int gate = n >> 5, j = n & 31;
        int phys = (j >> 3) * 24 + gate * 8 + (j & 7);
        d_Wp[(ih ? 0 : 3840) + phys * 40 + k] = __float2half_rn(ih ? wih[tt] : whh[tt]);
    } else {
        // h0: project node features + zero agg (8 rows per block)
        int hb = bid - (G_BLOCKS + BT_BLOCKS + WP_BLOCKS);
        int tid = threadIdx.x;
        for (int idx = tid; idx < 1024; idx += 256) { w1s[idx] = pw1[idx]; w2s[idx] = pw2[idx]; }
        if (tid < 32) { b1s[tid] = pb1[tid]; b2s[tid] = pb2[tid]; }
        __syncthreads();
        int row = hb * 8 + (tid >> 5);
        int j = tid & 31;
        float xj = x[(size_t)row * 32 + j];
        float a = b1s[j];
#pragma unroll
        for (int i = 0; i < 32; i++) a = fmaf(__shfl_sync(0xffffffffu, xj, i), w1s[i * 32 + j], a);
        a = fmaxf(a, 0.f);
        float o = b2s[j];
#pragma unroll
        for (int i = 0; i < 32; i++) o = fmaf(__shfl_sync(0xffffffffu, a, i), w2s[i * 32 + j], o);
        d_h[(size_t)row * 32 + j] = o;
        d_agg[(size_t)row * 32 + j] = 0.f;
    }
}

// ---------------- mma.sync helper ----------------
__device__ __forceinline__ void mma_f16(float& d0, float& d1, float& d2, float& d3,
                                        uint32_t a0, uint32_t a1, uint32_t a2, uint32_t a3,
                                        uint32_t b0, uint32_t b1) {
    asm volatile("mma.sync.aligned.m16n8k16.row.col.f32.f16.f16.f32 "
                 "{%0,%1,%2,%3}, {%4,%5,%6,%7}, {%8,%9}, {%0,%1,%2,%3};"
                 : "+f"(d0), "+f"(d1), "+f"(d2), "+f"(d3)
                 : "r"(a0), "r"(a1), "r"(a2), "r"(a3), "r"(b0), "r"(b1));
}

// ---------------- fused msg: D = (g ox x) @ W2^T via mma.sync, red-scatter ----------------
__global__ void __launch_bounds__(512, 1) msg_fused(const int* __restrict__ esrc,
                                                    const int* __restrict__ edst) {
    extern __shared__ char smem[];
    __half* Bs = (__half*)(smem + SM_B);
    __half* xs = (__half*)(smem + SM_X);
    __half* gs = (__half*)(smem + SM_G);
    int* srcs = (int*)(smem + SM_SRC);
    int* dsts = (int*)(smem + SM_DST);

    int tid = threadIdx.x;
    int w = tid >> 5, l = tid & 31;
    int e0 = blockIdx.x * EPC;

    { srcs[tid] = esrc[e0 + tid]; dsts[tid] = edst[e0 + tid]; }
    __syncthreads();

    // stage B: 4224 uint4 (32 rows x 132 uint4) from d_BT into padded rows
    for (int idx = tid; idx < 4224; idx += 512) {
        int o = idx / 132, c8 = (idx - o * 132) * 8;
        *(uint4*)(Bs + o * BSTRIDE + c8) = ((const uint4*)d_BT)[idx];
    }
    // stage x (both batches, gathered via src) as fp16: 4096 tasks
#pragma unroll
    for (int it = 0; it < 8; it++) {
        int t = tid + it * 512;
        int b = t >> 11, rq = t & 2047;
        int row = rq >> 2, qq = rq & 3;
        int src = srcs[row];
        const float4* p = (const float4*)(d_h + ((size_t)b * N_NODES + src) * 32 + qq * 8);
        float4 v0 = p[0], v1 = p[1];
        __half2 h0 = __floats2half2_rn(v0.x, v0.y), h1 = __floats2half2_rn(v0.z, v0.w);
        __half2 h2 = __floats2half2_rn(v1.x, v1.y), h3 = __floats2half2_rn(v1.z, v1.w);
        uint4 pk = { *(uint32_t*)&h0, *(uint32_t*)&h1, *(uint32_t*)&h2, *(uint32_t*)&h3 };
        *(uint4*)(xs + (b * 512 + row) * XSTRIDE + qq * 8) = pk;
    }
    // stage g as fp16: 2048 tasks
#pragma unroll
    for (int it = 0; it < 4; it++) {
        int t = tid + it * 512;
        int row = t >> 2, qq = t & 3;
        const float4* p = (const float4*)(d_g + (size_t)(e0 + row) * 32 + qq * 8);
        float4 v0 = p[0], v1 = p[1];
        __half2 h0 = __floats2half2_rn(v0.x, v0.y), h1 = __floats2half2_rn(v0.z, v0.w);
        __half2 h2 = __floats2half2_rn(v1.x, v1.y), h3 = __floats2half2_rn(v1.z, v1.w);
        uint4 pk = { *(uint32_t*)&h0, *(uint32_t*)&h1, *(uint32_t*)&h2, *(uint32_t*)&h3 };
        *(uint4*)(gs + row * XSTRIDE + qq * 8) = pk;
    }
    __syncthreads();

    int q = l & 3, r0 = l >> 2, q2 = q * 2;
    int rowbase = w * 32;
    int row4[4] = { rowbase + r0, rowbase + r0 + 8, rowbase + r0 + 16, rowbase + r0 + 24 };

    uint32_t xr[2][4][4];
#pragma unroll
    for (int b = 0; b < 2; b++)
#pragma unroll
        for (int i = 0; i < 4; i++) {
            const __half* xp = xs + (b * 512 + row4[i]) * XSTRIDE + q2;
#pragma unroll
            for (int p = 0; p < 4; p++) xr[b][i][p] = *(const uint32_t*)(xp + 8 * p);
        }

    float acc[2][2][4][4];
#pragma unroll
    for (int b = 0; b < 2; b++)
#pragma unroll
        for (int mt = 0; mt < 2; mt++)
#pragma unroll
            for (int nt = 0; nt < 4; nt++)
#pragma unroll
                for (int d = 0; d < 4; d++) acc[b][mt][nt][d] = 0.f;

    for (int kk = 0; kk < 33; kk++) {      // kk==32 -> bias block (A = x, no g)
        bool hasg = (kk < 32);
        __half2 g2[4];
        if (hasg) {
#pragma unroll
            for (int i = 0; i < 4; i++) g2[i] = __half2half2(gs[row4[i] * XSTRIDE + kk]);
        }
#pragma unroll
        for (int hh = 0; hh < 2; hh++) {
            int Kb = kk * 32 + hh * 16;
            uint32_t bf[4][2];
#pragma unroll
            for (int nt = 0; nt < 4; nt++) {
                const __half* bp = Bs + (nt * 8 + r0) * BSTRIDE + Kb + q2;
                bf[nt][0] = *(const uint32_t*)bp;
                bf[nt][1] = *(const uint32_t*)(bp + 8);
            }
#pragma unroll
            for (int b = 0; b < 2; b++) {
#pragma unroll
                for (int mt = 0; mt < 2; mt++) {
                    uint32_t a0 = xr[b][2 * mt][2 * hh],     a1 = xr[b][2 * mt + 1][2 * hh];
                    uint32_t a2 = xr[b][2 * mt][2 * hh + 1], a3 = xr[b][2 * mt + 1][2 * hh + 1];
                    if (hasg) {
                        __half2 gA = g2[2 * mt], gB = g2[2 * mt + 1];
                        __half2 t;
                        t = __hmul2(gA, *(__half2*)&a0); a0 = *(uint32_t*)&t;
                        t = __hmul2(gB, *(__half2*)&a1); a1 = *(uint32_t*)&t;
                        t = __hmul2(gA, *(__half2*)&a2); a2 = *(uint32_t*)&t;
                        t = __hmul2(gB, *(__half2*)&a3); a3 = *(uint32_t*)&t;
                    }
#pragma unroll
                    for (int nt = 0; nt < 4; nt++)
                        mma_f16(acc[b][mt][nt][0], acc[b][mt][nt][1], acc[b][mt][nt][2], acc[b][mt][nt][3],
                                a0, a1, a2, a3, bf[nt][0], bf[nt][1]);
                }
            }
        }
    }
#pragma unroll
    for (int b = 0; b < 2; b++)
#pragma unroll
        for (int mt = 0; mt < 2; mt++) {
            int dA = dsts[row4[2 * mt]], dB = dsts[row4[2 * mt + 1]];
            float* pA = d_agg + ((size_t)b * N_NODES + dA) * 32 + q2;
            float* pB = d_agg + ((size_t)b * N_NODES + dB) * 32 + q2;
#pragma unroll
            for (int nt = 0; nt < 4; nt++) {
                asm volatile("red.global.add.v2.f32 [%0], {%1,%2};"
                             :: "l"(pA + nt * 8), "f"(acc[b][mt][nt][0]), "f"(acc[b][mt][nt][1]) : "memory");
                asm volatile("red.global.add.v2.f32 [%0], {%1,%2};"
                             :: "l"(pB + nt * 8), "f"(acc[b][mt][nt][2]), "f"(acc[b][mt][nt][3]) : "memory");
            }
        }
}

// ---------------- GRU via mma.sync: 128 rows/CTA, 8 warps, precomputed weights ----------------
__global__ void __launch_bounds__(256, 3) gru_kernel(
                           const float* __restrict__ conv_b,
                           const float* __restrict__ bih, const float* __restrict__ bhh,
                           float* __restrict__ out, int last) {
    extern __shared__ char gsm[];
    __half* Bih = (__half*)(gsm + GW_OFF);
    __half* Bhh = Bih + 3840;
    __half* x16 = (__half*)(gsm + GX_OFF);
    __half* h16 = (__half*)(gsm + GH_OFF);
    float*  hf  = (float*)(gsm + GF_OFF);
    float*  bihs = (float*)(gsm + GBI_OFF);
    float*  bhhs = (float*)(gsm + GBH_OFF);
    float*  cbs  = (float*)(gsm + GCB_OFF);
    int tid = threadIdx.x;

    if (tid < 96) { bihs[tid] = bih[tid]; bhhs[tid] = bhh[tid]; }
    if (tid < 32) cbs[tid] = conv_b[tid];
    {
        const uint4* wsrc = (const uint4*)d_Wp;
        uint4* wdst = (uint4*)(gsm + GW_OFF);
#pragma unroll
        for (int it = 0; it < 4; it++) {
            int idx = tid + it * 256;
            if (idx < 960) wdst[idx] = wsrc[idx];
        }
    }
    __syncthreads();

    int row0 = blockIdx.x * 128;
#pragma unroll
    for (int it = 0; it < 4; it++) {
        int t = tid + it * 256;
        int rr = t >> 3, qq = t & 7;
        size_t off = (size_t)(row0 + rr) * 32 + qq * 4;
        float4 hv = *(const float4*)(d_h + off);
        float4 av = *(const float4*)(d_agg + off);
        *(float4*)(d_agg + off) = make_float4(0.f, 0.f, 0.f, 0.f);
        float4 cb4 = *(const float4*)&cbs[qq * 4];
        float x0 = fmaxf(av.x + cb4.x, 0.f), x1 = fmaxf(av.y + cb4.y, 0.f);
        float x2 = fmaxf(av.z + cb4.z, 0.f), x3 = fmaxf(av.w + cb4.w, 0.f);
        __half2 xa = __floats2half2_rn(x0, x1), xb = __floats2half2_rn(x2, x3);
        __half2 ha = __floats2half2_rn(hv.x, hv.y), hb = __floats2half2_rn(hv.z, hv.w);
        uint2 xpk = { *(uint32_t*)&xa, *(uint32_t*)&xb };
        uint2 hpk = { *(uint32_t*)&ha, *(uint32_t*)&hb };
        *(uint2*)(x16 + rr * 40 + qq * 4) = xpk;
        *(uint2*)(h16 + rr * 40 + qq * 4) = hpk;
        *(float2*)&hf[rr * GHS + qq * 4] = make_float2(hv.x, hv.y);
        *(float2*)&hf[rr * GHS + qq * 4 + 2] = make_float2(hv.z, hv.w);
    }
    __syncthreads();

    int w = tid >> 5, l = tid & 31;
    int q = l & 3, r0 = l >> 2, q2 = q * 2;
    int wrow = w * 16;
    float* dst = last ? out : (float*)d_h;

    uint32_t ax0[4], ax1[4], ah0[4], ah1[4];
    {
        const __half* xpl = x16 + (wrow + r0) * 40 + q2;
        const __half* xph = x16 + (wrow + r0 + 8) * 40 + q2;
        const __half* hpl = h16 + (wrow + r0) * 40 + q2;
        const __half* hph = h16 + (wrow + r0 + 8) * 40 + q2;
#pragma unroll
        for (int p = 0; p < 4; p++) {
            ax0[p] = *(const uint32_t*)(xpl + 8 * p);
            ax1[p] = *(const uint32_t*)(xph + 8 * p);
            ah0[p] = *(const uint32_t*)(hpl + 8 * p);
            ah1[p] = *(const uint32_t*)(hph + 8 * p);
        }
    }

#pragma unroll
    for (int jt = 0; jt < 4; jt++) {
        float ax[3][4], ah[3][4];
#pragma unroll
        for (int g = 0; g < 3; g++)
#pragma unroll
            for (int d = 0; d < 4; d++) { ax[g][d] = 0.f; ah[g][d] = 0.f; }
#pragma unroll
        for (int g = 0; g < 3; g++) {
            int phys = jt * 24 + g * 8 + r0;
            const __half* bi = Bih + phys * 40 + q2;
            const __half* bh = Bhh + phys * 40 + q2;
            uint32_t bi0 = *(const uint32_t*)bi,        bi1 = *(const uint32_t*)(bi + 8);
            uint32_t bi2 = *(const uint32_t*)(bi + 16), bi3 = *(const uint32_t*)(bi + 24);
            uint32_t bh0 = *(const uint32_t*)bh,        bh1 = *(const uint32_t*)(bh + 8);
            uint32_t bh2 = *(const uint32_t*)(bh + 16), bh3 = *(const uint32_t*)(bh + 24);
            mma_f16(ax[g][0], ax[g][1], ax[g][2], ax[g][3], ax0[0], ax1[0], ax0[1], ax1[1], bi0, bi1);
            mma_f16(ax[g][0], ax[g][1], ax[g][2], ax[g][3], ax0[2], ax1[2], ax0[3], ax1[3], bi2, bi3);
            mma_f16(ah[g][0], ah[g][1], ah[g][2], ah[g][3], ah0[0], ah1[0], ah0[1], ah1[1], bh0, bh1);
            mma_f16(ah[g][0], ah[g][1], ah[g][2], ah[g][3], ah0[2], ah1[2], ah0[3], ah1[3], bh2, bh3);
        }
        int colb = jt * 8 + q2;
        float bir0 = bihs[colb] + bhhs[colb],           bir1 = bihs[colb + 1] + bhhs[colb + 1];
        float biz0 = bihs[32 + colb] + bhhs[32 + colb], biz1 = bihs[33 + colb] + bhhs[33 + colb];
        float bxn0 = bihs[64 + colb], bxn1 = bihs[65 + colb];
        float bhn0 = bhhs[64 + colb], bhn1 = bhhs[65 + colb];
#pragma unroll
        for (int half = 0; half < 2; half++) {
            int row = wrow + r0 + half * 8;
            int d0 = half * 2, d1 = half * 2 + 1;
            float2 hv = *(const float2*)&hf[row * GHS + colb];
            float rg0 = sigm(ax[0][d0] + ah[0][d0] + bir0);
            float zg0 = sigm(ax[1][d0] + ah[1][d0] + biz0);
            float ng0 = fast_tanh(ax[2][d0] + bxn0 + rg0 * (ah[2][d0] + bhn0));
            float rg1 = sigm(ax[0][d1] + ah[0][d1] + bir1);
            float zg1 = sigm(ax[1][d1] + ah[1][d1] + biz1);
            float ng1 = fast_tanh(ax[2][d1] + bxn1 + rg1 * (ah[2][d1] + bhn1));
            float2 o;
            o.x = (1.f - zg0) * ng0 + zg0 * hv.x;
            o.y = (1.f - zg1) * ng1 + zg1 * hv.y;
            *(float2*)&dst[(size_t)(row0 + row) * 32 + colb] = o;
        }
    }
}

// ---------------- launch ----------------
extern "C" void kernel_launch(void* const* d_in, const int* in_sizes, int n_in,
                              void* d_out, int out_size) {
    const float* x     = (const float*)d_in[0];
    const float* er    = (const float*)d_in[1];
    const float* pw1   = (const float*)d_in[2];
    const float* pb1   = (const float*)d_in[3];
    const float* pw2   = (const float*)d_in[4];
    const float* pb2   = (const float*)d_in[5];
    const float* ew1   = (const float*)d_in[6];
    const float* eb1   = (const float*)d_in[7];
    const float* ew2   = (const float*)d_in[8];
    const float* eb2   = (const float*)d_in[9];
    const float* convb = (const float*)d_in[10];
    const float* wih   = (const float*)d_in[11];
    const float* whh   = (const float*)d_in[12];
    const float* bih   = (const float*)d_in[13];
    const float* bhh   = (const float*)d_in[14];
    const int*   esrc  = (const int*)d_in[15];
    const int*   edst  = (const int*)d_in[16];
    float* outp = (float*)d_out;

    cudaFuncSetAttribute(msg_fused, cudaFuncAttributeMaxDynamicSharedMemorySize, SM_TOTAL);
    cudaFuncSetAttribute(gru_kernel, cudaFuncAttributeMaxDynamicSharedMemorySize, G_TOTAL);

    prep_kernel<<<G_BLOCKS + BT_BLOCKS + WP_BLOCKS + H0_BLOCKS, 256>>>(
        er, ew1, eb1, ew2, eb2, wih, whh, x, pw1, pb1, pw2, pb2);
    for (int s = 0; s < 3; s++) {
        msg_fused<<<NTILES, 512, SM_TOTAL>>>(esrc, edst);
        gru_kernel<<<NROWS / 128, 256, G_TOTAL>>>(convb, bih, bhh, outp, s == 2 ? 1 : 0);
    }
}

// round 15
// speedup vs baseline: 1.5724x; 1.0225x over previous
#include <cuda_runtime.h>
#include <cuda_fp16.h>
#include <cstdint>

#define N_NODES 55296
#define N_EDGES 221184
#define NROWS   (2 * N_NODES)   /* B*N = 110592 */
#define EPC     512             /* edges per CTA */
#define NTILES  (N_EDGES / EPC) /* 432 */

// ---------------- scratch (device globals; no allocation) ----------------
__device__ float  d_g [(size_t)N_EDGES * 32];     // relu(edge MLP hidden)
__device__ float  d_h [(size_t)NROWS * 32];       // hidden/node carry
__device__ float  d_agg[(size_t)NROWS * 32];      // scatter accumulator
__device__ __half d_Bp[34048];                    // fragment-paired W2^T tile (32 rows x 1064 halves)
__device__ __half d_Wp[7680];                     // permuted GRU weights: [0,3840)=Wih, [3840,7680)=Whh, rows of 40

__device__ __forceinline__ float sigm(float x) {
    return __fdividef(1.f, 1.f + __expf(-x));
}
__device__ __forceinline__ float fast_tanh(float x) {
    float t = __expf(2.f * x);
    return 1.f - __fdividef(2.f, t + 1.f);
}

// smem layout for msg kernel (bytes), EPC=512
#define XSTRIDE 40       /* halves; 20 words mod 32 -> conflict-free */
#define SM_B    0        /* 32 rows x 1064 halves = 68096 (row stride 532 words; 532%32=20 -> LDS.64 conflict-free) */
#define SM_X    68096    /* 2*512 rows x 40 halves = 81920 */
#define SM_G    150016   /* 512 rows x 40 halves = 40960 */
#define SM_SRC  190976   /* 2048 */
#define SM_DST  193024   /* 2048 */
#define SM_TOTAL 195072

// smem layout for gru kernel (bytes), 128 rows/CTA
#define GHS     34       /* hf stride (floats) */
#define GW_OFF  0        /* 7680 halves = 15360 B (Wih @0, Whh @3840 halves) */
#define GX_OFF  15360    /* 128*40 halves = 10240 B */
#define GH_OFF  25600    /* 128*40 halves = 10240 B */
#define GF_OFF  35840    /* 128*34 floats = 17408 B */
#define GBI_OFF 53248    /* 96 floats */
#define GBH_OFF 53632    /* 96 floats */
#define GCB_OFF 54016    /* 32 floats */
#define G_TOTAL 54144

// ---------------- prep: g, Bp build, GRU weight permute, h0 projection (merged) ----------------
#define G_BLOCKS 27648   /* (N_EDGES*32)/256 */
#define BP_BLOCKS 133    /* ceil(34048/256) */
#define WP_BLOCKS 24     /* 6144/256 */
#define H0_BLOCKS (NROWS / 8)  /* 13824 */
__global__ void prep_kernel(const float* __restrict__ er,
                            const float* __restrict__ ew1, const float* __restrict__ eb1,
                            const float* __restrict__ ew2, const float* __restrict__ eb2,
                            const float* __restrict__ wih, const float* __restrict__ whh,
                            const float* __restrict__ x,
                            const float* __restrict__ pw1, const float* __restrict__ pb1,
                            const float* __restrict__ pw2, const float* __restrict__ pb2) {
    __shared__ float w1s[1024], w2s[1024], b1s[32], b2s[32];
    int bid = blockIdx.x;
    if (bid < G_BLOCKS) {
        int tid = bid * 256 + threadIdx.x;
        int e = tid >> 5, j = tid & 31;
        float4 rv = __ldg((const float4*)er + e);
        float a = __ldg(eb1 + j);
        a = fmaf(rv.x, __ldg(ew1 + j),      a);
        a = fmaf(rv.y, __ldg(ew1 + 32 + j), a);
        a = fmaf(rv.z, __ldg(ew1 + 64 + j), a);
        a = fmaf(rv.w, __ldg(ew1 + 96 + j), a);
        d_g[tid] = fmaxf(a, 0.f);
    } else if (bid < G_BLOCKS + BP_BLOCKS) {
        // Fragment-paired B: row n (output channel), offset t66*16 + q*4 + i holds
        // B[n][K] with K = t66*16 + q*2 + (i&1) + ((i>>1)<<3); B[n][K] = ew2[k,h*32+n] / eb2 tail.
        int t = (bid - G_BLOCKS) * 256 + threadIdx.x;
        if (t >= 34048) return;
        int n = t / 1064, rem = t % 1064;
        float f = 0.f;
        if (rem < 1056) {
            int t66 = rem >> 4, q = (rem >> 2) & 3, i = rem & 3;
            int K = t66 * 16 + q * 2 + (i & 1) + ((i >> 1) << 3);
            if (K < 1024) {
                int k = K >> 5, h = K & 31;
                f = ew2[k * 1024 + h * 32 + n];
            } else {
                f = eb2[(K - 1024) * 32 + n];
            }
        }
        d_Bp[t] = __float2half_rn(f);
    } else if (bid < G_BLOCKS + BP_BLOCKS + WP_BLOCKS) {
        // GRU weight permute: phys = (j>>3)*24 + gate*8 + (j&7) for logical n=gate*32+j
        int t = (bid - G_BLOCKS - BP_BLOCKS) * 256 + threadIdx.x;   // 0..6143
        if (t >= 6144) return;
        int ih = (t < 3072);
        int tt = ih ? t : t - 3072;
        int n = tt >> 5, k = tt & 31;
        int gate = n >> 5, j = n & 31;
        int phys = (j >> 3) * 24 + gate * 8 + (j & 7);
        d_Wp[(ih ? 0 : 3840) + phys * 40 + k] = __float2half_rn(ih ? wih[tt] : whh[tt]);
    } else {
        // h0: project node features + zero agg (8 rows per block)
        int hb = bid - (G_BLOCKS + BP_BLOCKS + WP_BLOCKS);
        int tid = threadIdx.x;
        for (int idx = tid; idx < 1024; idx += 256) { w1s[idx] = pw1[idx]; w2s[idx] = pw2[idx]; }
        if (tid < 32) { b1s[tid] = pb1[tid]; b2s[tid] = pb2[tid]; }
        __syncthreads();
        int row = hb * 8 + (tid >> 5);
        int j = tid & 31;
        float xj = x[(size_t)row * 32 + j];
        float a = b1s[j];
#pragma unroll
        for (int i = 0; i < 32; i++) a = fmaf(__shfl_sync(0xffffffffu, xj, i), w1s[i * 32 + j], a);
        a = fmaxf(a, 0.f);
        float o = b2s[j];
#pragma unroll
        for (int i = 0; i < 32; i++) o = fmaf(__shfl_sync(0xffffffffu, a, i), w2s[i * 32 + j], o);
        d_h[(size_t)row * 32 + j] = o;
        d_agg[(size_t)row * 32 + j] = 0.f;
    }
}

// ---------------- mma.sync helper ----------------
__device__ __forceinline__ void mma_f16(float& d0, float& d1, float& d2, float& d3,
                                        uint32_t a0, uint32_t a1, uint32_t a2, uint32_t a3,
                                        uint32_t b0, uint32_t b1) {
    asm volatile("mma.sync.aligned.m16n8k16.row.col.f32.f16.f16.f32 "
                 "{%0,%1,%2,%3}, {%4,%5,%6,%7}, {%8,%9}, {%0,%1,%2,%3};"
                 : "+f"(d0), "+f"(d1), "+f"(d2), "+f"(d3)
                 : "r"(a0), "r"(a1), "r"(a2), "r"(a3), "r"(b0), "r"(b1));
}

// ---------------- fused msg: D = (g ox x) @ W2^T via mma.sync, red-scatter ----------------
__global__ void __launch_bounds__(512, 1) msg_fused(const int* __restrict__ esrc,
                                                    const int* __restrict__ edst) {
    extern __shared__ char smem[];
    __half* xs = (__half*)(smem + SM_X);
    __half* gs = (__half*)(smem + SM_G);
    int* srcs = (int*)(smem + SM_SRC);
    int* dsts = (int*)(smem + SM_DST);

    int tid = threadIdx.x;
    int w = tid >> 5, l = tid & 31;
    int e0 = blockIdx.x * EPC;

    { srcs[tid] = esrc[e0 + tid]; dsts[tid] = edst[e0 + tid]; }
    __syncthreads();

    // stage B: straight copy of 4256 uint4 (fragment-paired layout, padding included)
    for (int idx = tid; idx < 4256; idx += 512) {
        ((uint4*)(smem + SM_B))[idx] = ((const uint4*)d_Bp)[idx];
    }
    // stage x (both batches, gathered via src) as fp16: 4096 tasks
#pragma unroll
    for (int it = 0; it < 8; it++) {
        int t = tid + it * 512;
        int b = t >> 11, rq = t & 2047;
        int row = rq >> 2, qq = rq & 3;
        int src = srcs[row];
        const float4* p = (const float4*)(d_h + ((size_t)b * N_NODES + src) * 32 + qq * 8);
        float4 v0 = p[0], v1 = p[1];
        __half2 h0 = __floats2half2_rn(v0.x, v0.y), h1 = __floats2half2_rn(v0.z, v0.w);
        __half2 h2 = __floats2half2_rn(v1.x, v1.y), h3 = __floats2half2_rn(v1.z, v1.w);
        uint4 pk = { *(uint32_t*)&h0, *(uint32_t*)&h1, *(uint32_t*)&h2, *(uint32_t*)&h3 };
        *(uint4*)(xs + (b * 512 + row) * XSTRIDE + qq * 8) = pk;
    }
    // stage g as fp16: 2048 tasks
#pragma unroll
    for (int it = 0; it < 4; it++) {
        int t = tid + it * 512;
        int row = t >> 2, qq = t & 3;
        const float4* p = (const float4*)(d_g + (size_t)(e0 + row) * 32 + qq * 8);
        float4 v0 = p[0], v1 = p[1];
        __half2 h0 = __floats2half2_rn(v0.x, v0.y), h1 = __floats2half2_rn(v0.z, v0.w);
        __half2 h2 = __floats2half2_rn(v1.x, v1.y), h3 = __floats2half2_rn(v1.z, v1.w);
        uint4 pk = { *(uint32_t*)&h0, *(uint32_t*)&h1, *(uint32_t*)&h2, *(uint32_t*)&h3 };
        *(uint4*)(gs + row * XSTRIDE + qq * 8) = pk;
    }
    __syncthreads();

    int q = l & 3, r0 = l >> 2, q2 = q * 2;
    int rowbase = w * 32;
    int row4[4] = { rowbase + r0, rowbase + r0 + 8, rowbase + r0 + 16, rowbase + r0 + 24 };
    const uint2* Bp2 = (const uint2*)(smem + SM_B);   // row stride 266 uint2 (= 1064 halves)

    uint32_t xr[2][4][4];
#pragma unroll
    for (int b = 0; b < 2; b++)
#pragma unroll
        for (int i = 0; i < 4; i++) {
            const __half* xp = xs + (b * 512 + row4[i]) * XSTRIDE + q2;
#pragma unroll
            for (int p = 0; p < 4; p++) xr[b][i][p] = *(const uint32_t*)(xp + 8 * p);
        }

    float acc[2][2][4][4];
#pragma unroll
    for (int b = 0; b < 2; b++)
#pragma unroll
        for (int mt = 0; mt < 2; mt++)
#pragma unroll
            for (int nt = 0; nt < 4; nt++)
#pragma unroll
                for (int d = 0; d < 4; d++) acc[b][mt][nt][d] = 0.f;

#pragma unroll 3
    for (int kk = 0; kk < 33; kk++) {      // kk==32 -> bias block (A = x, no g)
        bool hasg = (kk < 32);
        __half2 g2[4];
        if (hasg) {
#pragma unroll
            for (int i = 0; i < 4; i++) g2[i] = __half2half2(gs[row4[i] * XSTRIDE + kk]);
        }
#pragma unroll
        for (int hh = 0; hh < 2; hh++) {
            int tb = (kk * 2 + hh) * 4 + q;
            uint32_t bf[4][2];
#pragma unroll
            for (int nt = 0; nt < 4; nt++) {
                uint2 v = Bp2[(nt * 8 + r0) * 266 + tb];   // one LDS.64, conflict-free
                bf[nt][0] = v.x;
                bf[nt][1] = v.y;
            }
#pragma unroll
            for (int b = 0; b < 2; b++) {
#pragma unroll
                for (int mt = 0; mt < 2; mt++) {
                    uint32_t a0 = xr[b][2 * mt][2 * hh],     a1 = xr[b][2 * mt + 1][2 * hh];
                    uint32_t a2 = xr[b][2 * mt][2 * hh + 1], a3 = xr[b][2 * mt + 1][2 * hh + 1];
                    if (hasg) {
                        __half2 gA = g2[2 * mt], gB = g2[2 * mt + 1];
                        __half2 t;
                        t = __hmul2(gA, *(__half2*)&a0); a0 = *(uint32_t*)&t;
                        t = __hmul2(gB, *(__half2*)&a1); a1 = *(uint32_t*)&t;
                        t = __hmul2(gA, *(__half2*)&a2); a2 = *(uint32_t*)&t;
                        t = __hmul2(gB, *(__half2*)&a3); a3 = *(uint32_t*)&t;
                    }
#pragma unroll
                    for (int nt = 0; nt < 4; nt++)
                        mma_f16(acc[b][mt][nt][0], acc[b][mt][nt][1], acc[b][mt][nt][2], acc[b][mt][nt][3],
                                a0, a1, a2, a3, bf[nt][0], bf[nt][1]);
                }
            }
        }
    }
#pragma unroll
    for (int b = 0; b < 2; b++)
#pragma unroll
        for (int mt = 0; mt < 2; mt++) {
            int dA = dsts[row4[2 * mt]], dB = dsts[row4[2 * mt + 1]];
            float* pA = d_agg + ((size_t)b * N_NODES + dA) * 32 + q2;
            float* pB = d_agg + ((size_t)b * N_NODES + dB) * 32 + q2;
#pragma unroll
            for (int nt = 0; nt < 4; nt++) {
                asm volatile("red.global.add.v2.f32 [%0], {%1,%2};"
                             :: "l"(pA + nt * 8), "f"(acc[b][mt][nt][0]), "f"(acc[b][mt][nt][1]) : "memory");
                asm volatile("red.global.add.v2.f32 [%0], {%1,%2};"
                             :: "l"(pB + nt * 8), "f"(acc[b][mt][nt][2]), "f"(acc[b][mt][nt][3]) : "memory");
            }
        }
}

// ---------------- GRU via mma.sync: 128 rows/CTA, 8 warps, precomputed weights ----------------
__global__ void __launch_bounds__(256, 3) gru_kernel(
                           const float* __restrict__ conv_b,
                           const float* __restrict__ bih, const float* __restrict__ bhh,
                           float* __restrict__ out, int last) {
    extern __shared__ char gsm[];
    __half* Bih = (__half*)(gsm + GW_OFF);
    __half* Bhh = Bih + 3840;
    __half* x16 = (__half*)(gsm + GX_OFF);
    __half* h16 = (__half*)(gsm + GH_OFF);
    float*  hf  = (float*)(gsm + GF_OFF);
    float*  bihs = (float*)(gsm + GBI_OFF);
    float*  bhhs = (float*)(gsm + GBH_OFF);
    float*  cbs  = (float*)(gsm + GCB_OFF);
    int tid = threadIdx.x;

    if (tid < 96) { bihs[tid] = bih[tid]; bhhs[tid] = bhh[tid]; }
    if (tid < 32) cbs[tid] = conv_b[tid];
    {
        const uint4* wsrc = (const uint4*)d_Wp;
        uint4* wdst = (uint4*)(gsm + GW_OFF);
#pragma unroll
        for (int it = 0; it < 4; it++) {
            int idx = tid + it * 256;
            if (idx < 960) wdst[idx] = wsrc[idx];
        }
    }
    __syncthreads();

    int row0 = blockIdx.x * 128;
#pragma unroll
    for (int it = 0; it < 4; it++) {
        int t = tid + it * 256;
        int rr = t >> 3, qq = t & 7;
        size_t off = (size_t)(row0 + rr) * 32 + qq * 4;
        float4 hv = *(const float4*)(d_h + off);
        float4 av = *(const float4*)(d_agg + off);
        *(float4*)(d_agg + off) = make_float4(0.f, 0.f, 0.f, 0.f);
        float4 cb4 = *(const float4*)&cbs[qq * 4];
        float x0 = fmaxf(av.x + cb4.x, 0.f), x1 = fmaxf(av.y + cb4.y, 0.f);
        float x2 = fmaxf(av.z + cb4.z, 0.f), x3 = fmaxf(av.w + cb4.w, 0.f);
        __half2 xa = __floats2half2_rn(x0, x1), xb = __floats2half2_rn(x2, x3);
        __half2 ha = __floats2half2_rn(hv.x, hv.y), hb = __floats2half2_rn(hv.z, hv.w);
        uint2 xpk = { *(uint32_t*)&xa, *(uint32_t*)&xb };
        uint2 hpk = { *(uint32_t*)&ha, *(uint32_t*)&hb };
        *(uint2*)(x16 + rr * 40 + qq * 4) = xpk;
        *(uint2*)(h16 + rr * 40 + qq * 4) = hpk;
        *(float2*)&hf[rr * GHS + qq * 4] = make_float2(hv.x, hv.y);
        *(float2*)&hf[rr * GHS + qq * 4 + 2] = make_float2(hv.z, hv.w);
    }
    __syncthreads();

    int w = tid >> 5, l = tid & 31;
    int q = l & 3, r0 = l >> 2, q2 = q * 2;
    int wrow = w * 16;
    float* dst = last ? out : (float*)d_h;

    uint32_t ax0[4], ax1[4], ah0[4], ah1[4];
    {
        const __half* xpl = x16 + (wrow + r0) * 40 + q2;
        const __half* xph = x16 + (wrow + r0 + 8) * 40 + q2;
        const __half* hpl = h16 + (wrow + r0) * 40 + q2;
        const __half* hph = h16 + (wrow + r0 + 8) * 40 + q2;
#pragma unroll
        for (int p = 0; p < 4; p++) {
            ax0[p] = *(const uint32_t*)(xpl + 8 * p);
            ax1[p] = *(const uint32_t*)(xph + 8 * p);
            ah0[p] = *(const uint32_t*)(hpl + 8 * p);
            ah1[p] = *(const uint32_t*)(hph + 8 * p);
        }
    }

#pragma unroll
    for (int jt = 0; jt < 4; jt++) {
        float ax[3][4], ah[3][4];
#pragma unroll
        for (int g = 0; g < 3; g++)
#pragma unroll
            for (int d = 0; d < 4; d++) { ax[g][d] = 0.f; ah[g][d] = 0.f; }
#pragma unroll
        for (int g = 0; g < 3; g++) {
            int phys = jt * 24 + g * 8 + r0;
            const __half* bi = Bih + phys * 40 + q2;
            const __half* bh = Bhh + phys * 40 + q2;
            uint32_t bi0 = *(const uint32_t*)bi,        bi1 = *(const uint32_t*)(bi + 8);
            uint32_t bi2 = *(const uint32_t*)(bi + 16), bi3 = *(const uint32_t*)(bi + 24);
            uint32_t bh0 = *(const uint32_t*)bh,        bh1 = *(const uint32_t*)(bh + 8);
            uint32_t bh2 = *(const uint32_t*)(bh + 16), bh3 = *(const uint32_t*)(bh + 24);
            mma_f16(ax[g][0], ax[g][1], ax[g][2], ax[g][3], ax0[0], ax1[0], ax0[1], ax1[1], bi0, bi1);
            mma_f16(ax[g][0], ax[g][1], ax[g][2], ax[g][3], ax0[2], ax1[2], ax0[3], ax1[3], bi2, bi3);
            mma_f16(ah[g][0], ah[g][1], ah[g][2], ah[g][3], ah0[0], ah1[0], ah0[1], ah1[1], bh0, bh1);
            mma_f16(ah[g][0], ah[g][1], ah[g][2], ah[g][3], ah0[2], ah1[2], ah0[3], ah1[3], bh2, bh3);
        }
        int colb = jt * 8 + q2;
        float bir0 = bihs[colb] + bhhs[colb],           bir1 = bihs[colb + 1] + bhhs[colb + 1];
        float biz0 = bihs[32 + colb] + bhhs[32 + colb], biz1 = bihs[33 + colb] + bhhs[33 + colb];
        float bxn0 = bihs[64 + colb], bxn1 = bihs[65 + colb];
        float bhn0 = bhhs[64 + colb], bhn1 = bhhs[65 + colb];
#pragma unroll
        for (int half = 0; half < 2; half++) {
            int row = wrow + r0 + half * 8;
            int d0 = half * 2, d1 = half * 2 + 1;
            float2 hv = *(const float2*)&hf[row * GHS + colb];
            float rg0 = sigm(ax[0][d0] + ah[0][d0] + bir0);
            float zg0 = sigm(ax[1][d0] + ah[1][d0] + biz0);
            float ng0 = fast_tanh(ax[2][d0] + bxn0 + rg0 * (ah[2][d0] + bhn0));
            float rg1 = sigm(ax[0][d1] + ah[0][d1] + bir1);
            float zg1 = sigm(ax[1][d1] + ah[1][d1] + biz1);
            float ng1 = fast_tanh(ax[2][d1] + bxn1 + rg1 * (ah[2][d1] + bhn1));
            float2 o;
            o.x = (1.f - zg0) * ng0 + zg0 * hv.x;
            o.y = (1.f - zg1) * ng1 + zg1 * hv.y;
            *(float2*)&dst[(size_t)(row0 + row) * 32 + colb] = o;
        }
    }
}

// ---------------- launch ----------------
extern "C" void kernel_launch(void* const* d_in, const int* in_sizes, int n_in,
                              void* d_out, int out_size) {
    const float* x     = (const float*)d_in[0];
    const float* er    = (const float*)d_in[1];
    const float* pw1   = (const float*)d_in[2];
    const float* pb1   = (const float*)d_in[3];
    const float* pw2   = (const float*)d_in[4];
    const float* pb2   = (const float*)d_in[5];
    const float* ew1   = (const float*)d_in[6];
    const float* eb1   = (const float*)d_in[7];
    const float* ew2   = (const float*)d_in[8];
    const float* eb2   = (const float*)d_in[9];
    const float* convb = (const float*)d_in[10];
    const float* wih   = (const float*)d_in[11];
    const float* whh   = (const float*)d_in[12];
    const float* bih   = (const float*)d_in[13];
    const float* bhh   = (const float*)d_in[14];
    const int*   esrc  = (const int*)d_in[15];
    const int*   edst  = (const int*)d_in[16];
    float* outp = (float*)d_out;

    cudaFuncSetAttribute(msg_fused, cudaFuncAttributeMaxDynamicSharedMemorySize, SM_TOTAL);
    cudaFuncSetAttribute(gru_kernel, cudaFuncAttributeMaxDynamicSharedMemorySize, G_TOTAL);

    prep_kernel<<<G_BLOCKS + BP_BLOCKS + WP_BLOCKS + H0_BLOCKS, 256>>>(
        er, ew1, eb1, ew2, eb2, wih, whh, x, pw1, pb1, pw2, pb2);
    for (int s = 0; s < 3; s++) {
        msg_fused<<<NTILES, 512, SM_TOTAL>>>(esrc, edst);
        gru_kernel<<<NROWS / 128, 256, G_TOTAL>>>(convb, bih, bhh, outp, s == 2 ? 1 : 0);
    }
}

// round 16
// speedup vs baseline: 1.5743x; 1.0012x over previous
#include <cuda_runtime.h>
#include <cuda_fp16.h>
#include <cstdint>

#define N_NODES 55296
#define N_EDGES 221184
#define NROWS   (2 * N_NODES)   /* B*N = 110592 */
#define EPC     512             /* edges per CTA */
#define NTILES  (N_EDGES / EPC) /* 432 */

// ---------------- scratch (device globals; no allocation) ----------------
__device__ __half d_g16[(size_t)N_EDGES * 32];    // relu(edge MLP hidden), fp16
__device__ float  d_h  [(size_t)NROWS * 32];      // hidden/node carry (fp32)
__device__ __half d_h16[(size_t)NROWS * 32];      // fp16 mirror of d_h (for msg gather)
__device__ float  d_agg[(size_t)NROWS * 32];      // scatter accumulator
__device__ __half d_Bp[34048];                    // fragment-paired W2^T tile (32 rows x 1064 halves)
__device__ __half d_Wp[7680];                     // permuted GRU weights: [0,3840)=Wih, [3840,7680)=Whh, rows of 40

__device__ __forceinline__ float sigm(float x) {
    return __fdividef(1.f, 1.f + __expf(-x));
}
__device__ __forceinline__ float fast_tanh(float x) {
    float t = __expf(2.f * x);
    return 1.f - __fdividef(2.f, t + 1.f);
}

// smem layout for msg kernel (bytes), EPC=512
#define XSTRIDE 40       /* halves; 20 words mod 32 -> conflict-free */
#define SM_B    0        /* 32 rows x 1064 halves = 68096 (row stride 532 words; 532%32=20 -> LDS.64 conflict-free) */
#define SM_X    68096    /* 2*512 rows x 40 halves = 81920 */
#define SM_G    150016   /* 512 rows x 40 halves = 40960 */
#define SM_SRC  190976   /* 2048 */
#define SM_DST  193024   /* 2048 */
#define SM_TOTAL 195072

// smem layout for gru kernel (bytes), 128 rows/CTA
#define GHS     34       /* hf stride (floats) */
#define GW_OFF  0        /* 7680 halves = 15360 B (Wih @0, Whh @3840 halves) */
#define GX_OFF  15360    /* 128*40 halves = 10240 B */
#define GH_OFF  25600    /* 128*40 halves = 10240 B */
#define GF_OFF  35840    /* 128*34 floats = 17408 B */
#define GBI_OFF 53248    /* 96 floats */
#define GBH_OFF 53632    /* 96 floats */
#define GCB_OFF 54016    /* 32 floats */
#define G_TOTAL 54144

// ---------------- prep: g, Bp build, GRU weight permute, h0 projection (merged) ----------------
#define G_BLOCKS 27648   /* (N_EDGES*32)/256 */
#define BP_BLOCKS 133    /* ceil(34048/256) */
#define WP_BLOCKS 24     /* 6144/256 */
#define H0_BLOCKS (NROWS / 8)  /* 13824 */
__global__ void prep_kernel(const float* __restrict__ er,
                            const float* __restrict__ ew1, const float* __restrict__ eb1,
                            const float* __restrict__ ew2, const float* __restrict__ eb2,
                            const float* __restrict__ wih, const float* __restrict__ whh,
                            const float* __restrict__ x,
                            const float* __restrict__ pw1, const float* __restrict__ pb1,
                            const float* __restrict__ pw2, const float* __restrict__ pb2) {
    __shared__ float w1s[1024], w2s[1024], b1s[32], b2s[32];
    int bid = blockIdx.x;
    if (bid < G_BLOCKS) {
        int tid = bid * 256 + threadIdx.x;
        int e = tid >> 5, j = tid & 31;
        float4 rv = __ldg((const float4*)er + e);
        float a = __ldg(eb1 + j);
        a = fmaf(rv.x, __ldg(ew1 + j),      a);
        a = fmaf(rv.y, __ldg(ew1 + 32 + j), a);
        a = fmaf(rv.z, __ldg(ew1 + 64 + j), a);
        a = fmaf(rv.w, __ldg(ew1 + 96 + j), a);
        d_g16[tid] = __float2half_rn(fmaxf(a, 0.f));
    } else if (bid < G_BLOCKS + BP_BLOCKS) {
        // Fragment-paired B: row n (output channel), offset t66*16 + q*4 + i holds
        // B[n][K] with K = t66*16 + q*2 + (i&1) + ((i>>1)<<3); B[n][K] = ew2[k,h*32+n] / eb2 tail.
        int t = (bid - G_BLOCKS) * 256 + threadIdx.x;
        if (t >= 34048) return;
        int n = t / 1064, rem = t % 1064;
        float f = 0.f;
        if (rem < 1056) {
            int t66 = rem >> 4, q = (rem >> 2) & 3, i = rem & 3;
            int K = t66 * 16 + q * 2 + (i & 1) + ((i >> 1) << 3);
            if (K < 1024) {
                int k = K >> 5, h = K & 31;
                f = ew2[k * 1024 + h * 32 + n];
            } else {
                f = eb2[(K - 1024) * 32 + n];
            }
        }
        d_Bp[t] = __float2half_rn(f);
    } else if (bid < G_BLOCKS + BP_BLOCKS + WP_BLOCKS) {
        // GRU weight permute: phys = (j>>3)*24 + gate*8 + (j&7) for logical n=gate*32+j
        int t = (bid - G_BLOCKS - BP_BLOCKS) * 256 + threadIdx.x;   // 0..6143
        if (t >= 6144) return;
        int ih = (t < 3072);
        int tt = ih ? t : t - 3072;
        int n = tt >> 5, k = tt & 31;
        int gate = n >> 5, j = n & 31;
        int phys = (j >> 3) * 24 + gate * 8 + (j & 7);
        d_Wp[(ih ? 0 : 3840) + phys * 40 + k] = __float2half_rn(ih ? wih[tt] : whh[tt]);
    } else {
        // h0: project node features + zero agg (8 rows per block)
        int hb = bid - (G_BLOCKS + BP_BLOCKS + WP_BLOCKS);
        int tid = threadIdx.x;
        for (int idx = tid; idx < 1024; idx += 256) { w1s[idx] = pw1[idx]; w2s[idx] = pw2[idx]; }
        if (tid < 32) { b1s[tid] = pb1[tid]; b2s[tid] = pb2[tid]; }
        __syncthreads();
        int row = hb * 8 + (tid >> 5);
        int j = tid & 31;
        float xj = x[(size_t)row * 32 + j];
        float a = b1s[j];
#pragma unroll
        for (int i = 0; i < 32; i++) a = fmaf(__shfl_sync(0xffffffffu, xj, i), w1s[i * 32 + j], a);
        a = fmaxf(a, 0.f);
        float o = b2s[j];
#pragma unroll
        for (int i = 0; i < 32; i++) o = fmaf(__shfl_sync(0xffffffffu, a, i), w2s[i * 32 + j], o);
        d_h[(size_t)row * 32 + j] = o;
        d_h16[(size_t)row * 32 + j] = __float2half_rn(o);
        d_agg[(size_t)row * 32 + j] = 0.f;
    }
}

// ---------------- mma.sync helper ----------------
__device__ __forceinline__ void mma_f16(float& d0, float& d1, float& d2, float& d3,
                                        uint32_t a0, uint32_t a1, uint32_t a2, uint32_t a3,
                                        uint32_t b0, uint32_t b1) {
    asm volatile("mma.sync.aligned.m16n8k16.row.col.f32.f16.f16.f32 "
                 "{%0,%1,%2,%3}, {%4,%5,%6,%7}, {%8,%9}, {%0,%1,%2,%3};"
                 : "+f"(d0), "+f"(d1), "+f"(d2), "+f"(d3)
                 : "r"(a0), "r"(a1), "r"(a2), "r"(a3), "r"(b0), "r"(b1));
}

// ---------------- fused msg: D = (g ox x) @ W2^T via mma.sync, red-scatter ----------------
__global__ void __launch_bounds__(512, 1) msg_fused(const int* __restrict__ esrc,
                                                    const int* __restrict__ edst) {
    extern __shared__ char smem[];
    __half* xs = (__half*)(smem + SM_X);
    __half* gs = (__half*)(smem + SM_G);
    int* srcs = (int*)(smem + SM_SRC);
    int* dsts = (int*)(smem + SM_DST);

    int tid = threadIdx.x;
    int w = tid >> 5, l = tid & 31;
    int e0 = blockIdx.x * EPC;

    { srcs[tid] = esrc[e0 + tid]; dsts[tid] = edst[e0 + tid]; }
    __syncthreads();

    // stage B: straight copy of 4256 uint4 (fragment-paired layout, padding included)
    for (int idx = tid; idx < 4256; idx += 512) {
        ((uint4*)(smem + SM_B))[idx] = ((const uint4*)d_Bp)[idx];
    }
    // stage x (both batches, gathered via src) from fp16 mirror: 4096 uint4 copies
#pragma unroll
    for (int it = 0; it < 8; it++) {
        int t = tid + it * 512;
        int b = t >> 11, rq = t & 2047;
        int row = rq >> 2, qq = rq & 3;
        int src = srcs[row];
        uint4 v = *(const uint4*)(d_h16 + ((size_t)b * N_NODES + src) * 32 + qq * 8);
        *(uint4*)(xs + (b * 512 + row) * XSTRIDE + qq * 8) = v;
    }
    // stage g from fp16: 2048 uint4 copies
#pragma unroll
    for (int it = 0; it < 4; it++) {
        int t = tid + it * 512;
        int row = t >> 2, qq = t & 3;
        uint4 v = *(const uint4*)(d_g16 + (size_t)(e0 + row) * 32 + qq * 8);
        *(uint4*)(gs + row * XSTRIDE + qq * 8) = v;
    }
    __syncthreads();

    int q = l & 3, r0 = l >> 2, q2 = q * 2;
    int rowbase = w * 32;
    int row4[4] = { rowbase + r0, rowbase + r0 + 8, rowbase + r0 + 16, rowbase + r0 + 24 };
    const uint2* Bp2 = (const uint2*)(smem + SM_B);   // row stride 266 uint2 (= 1064 halves)

    uint32_t xr[2][4][4];
#pragma unroll
    for (int b = 0; b < 2; b++)
#pragma unroll
        for (int i = 0; i < 4; i++) {
            const __half* xp = xs + (b * 512 + row4[i]) * XSTRIDE + q2;
#pragma unroll
            for (int p = 0; p < 4; p++) xr[b][i][p] = *(const uint32_t*)(xp + 8 * p);
        }

    float acc[2][2][4][4];
#pragma unroll
    for (int b = 0; b < 2; b++)
#pragma unroll
        for (int mt = 0; mt < 2; mt++)
#pragma unroll
            for (int nt = 0; nt < 4; nt++)
#pragma unroll
                for (int d = 0; d < 4; d++) acc[b][mt][nt][d] = 0.f;

#pragma unroll 3
    for (int kk = 0; kk < 33; kk++) {      // kk==32 -> bias block (A = x, no g)
        bool hasg = (kk < 32);
        __half2 g2[4];
        if (hasg) {
#pragma unroll
            for (int i = 0; i < 4; i++) g2[i] = __half2half2(gs[row4[i] * XSTRIDE + kk]);
        }
#pragma unroll
        for (int hh = 0; hh < 2; hh++) {
            int tb = (kk * 2 + hh) * 4 + q;
            uint32_t bf[4][2];
#pragma unroll
            for (int nt = 0; nt < 4; nt++) {
                uint2 v = Bp2[(nt * 8 + r0) * 266 + tb];   // one LDS.64, conflict-free
                bf[nt][0] = v.x;
                bf[nt][1] = v.y;
            }
#pragma unroll
            for (int b = 0; b < 2; b++) {
#pragma unroll
                for (int mt = 0; mt < 2; mt++) {
                    uint32_t a0 = xr[b][2 * mt][2 * hh],     a1 = xr[b][2 * mt + 1][2 * hh];
                    uint32_t a2 = xr[b][2 * mt][2 * hh + 1], a3 = xr[b][2 * mt + 1][2 * hh + 1];
                    if (hasg) {
                        __half2 gA = g2[2 * mt], gB = g2[2 * mt + 1];
                        __half2 t;
                        t = __hmul2(gA, *(__half2*)&a0); a0 = *(uint32_t*)&t;
                        t = __hmul2(gB, *(__half2*)&a1); a1 = *(uint32_t*)&t;
                        t = __hmul2(gA, *(__half2*)&a2); a2 = *(uint32_t*)&t;
                        t = __hmul2(gB, *(__half2*)&a3); a3 = *(uint32_t*)&t;
                    }
#pragma unroll
                    for (int nt = 0; nt < 4; nt++)
                        mma_f16(acc[b][mt][nt][0], acc[b][mt][nt][1], acc[b][mt][nt][2], acc[b][mt][nt][3],
                                a0, a1, a2, a3, bf[nt][0], bf[nt][1]);
                }
            }
        }
    }
#pragma unroll
    for (int b = 0; b < 2; b++)
#pragma unroll
        for (int mt = 0; mt < 2; mt++) {
            int dA = dsts[row4[2 * mt]], dB = dsts[row4[2 * mt + 1]];
            float* pA = d_agg + ((size_t)b * N_NODES + dA) * 32 + q2;
            float* pB = d_agg + ((size_t)b * N_NODES + dB) * 32 + q2;
#pragma unroll
            for (int nt = 0; nt < 4; nt++) {
                asm volatile("red.global.add.v2.f32 [%0], {%1,%2};"
                             :: "l"(pA + nt * 8), "f"(acc[b][mt][nt][0]), "f"(acc[b][mt][nt][1]) : "memory");
                asm volatile("red.global.add.v2.f32 [%0], {%1,%2};"
                             :: "l"(pB + nt * 8), "f"(acc[b][mt][nt][2]), "f"(acc[b][mt][nt][3]) : "memory");
            }
        }
}

// ---------------- GRU via mma.sync: 128 rows/CTA, 8 warps, precomputed weights ----------------
__global__ void __launch_bounds__(256, 3) gru_kernel(
                           const float* __restrict__ conv_b,
                           const float* __restrict__ bih, const float* __restrict__ bhh,
                           float* __restrict__ out, int last) {
    extern __shared__ char gsm[];
    __half* Bih = (__half*)(gsm + GW_OFF);
    __half* Bhh = Bih + 3840;
    __half* x16 = (__half*)(gsm + GX_OFF);
    __half* h16 = (__half*)(gsm + GH_OFF);
    float*  hf  = (float*)(gsm + GF_OFF);
    float*  bihs = (float*)(gsm + GBI_OFF);
    float*  bhhs = (float*)(gsm + GBH_OFF);
    float*  cbs  = (float*)(gsm + GCB_OFF);
    int tid = threadIdx.x;

    if (tid < 96) { bihs[tid] = bih[tid]; bhhs[tid] = bhh[tid]; }
    if (tid < 32) cbs[tid] = conv_b[tid];
    {
        const uint4* wsrc = (const uint4*)d_Wp;
        uint4* wdst = (uint4*)(gsm + GW_OFF);
#pragma unroll
        for (int it = 0; it < 4; it++) {
            int idx = tid + it * 256;
            if (idx < 960) wdst[idx] = wsrc[idx];
        }
    }
    __syncthreads();

    int row0 = blockIdx.x * 128;
#pragma unroll
    for (int it = 0; it < 4; it++) {
        int t = tid + it * 256;
        int rr = t >> 3, qq = t & 7;
        size_t off = (size_t)(row0 + rr) * 32 + qq * 4;
        float4 hv = *(const float4*)(d_h + off);
        float4 av = *(const float4*)(d_agg + off);
        *(float4*)(d_agg + off) = make_float4(0.f, 0.f, 0.f, 0.f);
        float4 cb4 = *(const float4*)&cbs[qq * 4];
        float x0 = fmaxf(av.x + cb4.x, 0.f), x1 = fmaxf(av.y + cb4.y, 0.f);
        float x2 = fmaxf(av.z + cb4.z, 0.f), x3 = fmaxf(av.w + cb4.w, 0.f);
        __half2 xa = __floats2half2_rn(x0, x1), xb = __floats2half2_rn(x2, x3);
        __half2 ha = __floats2half2_rn(hv.x, hv.y), hb = __floats2half2_rn(hv.z, hv.w);
        uint2 xpk = { *(uint32_t*)&xa, *(uint32_t*)&xb };
        uint2 hpk = { *(uint32_t*)&ha, *(uint32_t*)&hb };
        *(uint2*)(x16 + rr * 40 + qq * 4) = xpk;
        *(uint2*)(h16 + rr * 40 + qq * 4) = hpk;
        *(float2*)&hf[rr * GHS + qq * 4] = make_float2(hv.x, hv.y);
        *(float2*)&hf[rr * GHS + qq * 4 + 2] = make_float2(hv.z, hv.w);
    }
    __syncthreads();

    int w = tid >> 5, l = tid & 31;
    int q = l & 3, r0 = l >> 2, q2 = q * 2;
    int wrow = w * 16;
    float* dst = last ? out : (float*)d_h;

    uint32_t ax0[4], ax1[4], ah0[4], ah1[4];
    {
        const __half* xpl = x16 + (wrow + r0) * 40 + q2;
        const __half* xph = x16 + (wrow + r0 + 8) * 40 + q2;
        const __half* hpl = h16 + (wrow + r0) * 40 + q2;
        const __half* hph = h16 + (wrow + r0 + 8) * 40 + q2;
#pragma unroll
        for (int p = 0; p < 4; p++) {
            ax0[p] = *(const uint32_t*)(xpl + 8 * p);
            ax1[p] = *(const uint32_t*)(xph + 8 * p);
            ah0[p] = *(const uint32_t*)(hpl + 8 * p);
            ah1[p] = *(const uint32_t*)(hph + 8 * p);
        }
    }

#pragma unroll
    for (int jt = 0; jt < 4; jt++) {
        float ax[3][4], ah[3][4];
#pragma unroll
        for (int g = 0; g < 3; g++)
#pragma unroll
            for (int d = 0; d < 4; d++) { ax[g][d] = 0.f; ah[g][d] = 0.f; }
#pragma unroll
        for (int g = 0; g < 3; g++) {
            int phys = jt * 24 + g * 8 + r0;
            const __half* bi = Bih + phys * 40 + q2;
            const __half* bh = Bhh + phys * 40 + q2;
            uint32_t bi0 = *(const uint32_t*)bi,        bi1 = *(const uint32_t*)(bi + 8);
            uint32_t bi2 = *(const uint32_t*)(bi + 16), bi3 = *(const uint32_t*)(bi + 24);
            uint32_t bh0 = *(const uint32_t*)bh,        bh1 = *(const uint32_t*)(bh + 8);
            uint32_t bh2 = *(const uint32_t*)(bh + 16), bh3 = *(const uint32_t*)(bh + 24);
            mma_f16(ax[g][0], ax[g][1], ax[g][2], ax[g][3], ax0[0], ax1[0], ax0[1], ax1[1], bi0, bi1);
            mma_f16(ax[g][0], ax[g][1], ax[g][2], ax[g][3], ax0[2], ax1[2], ax0[3], ax1[3], bi2, bi3);
            mma_f16(ah[g][0], ah[g][1], ah[g][2], ah[g][3], ah0[0], ah1[0], ah0[1], ah1[1], bh0, bh1);
            mma_f16(ah[g][0], ah[g][1], ah[g][2], ah[g][3], ah0[2], ah1[2], ah0[3], ah1[3], bh2, bh3);
        }
        int colb = jt * 8 + q2;
        float bir0 = bihs[colb] + bhhs[colb],           bir1 = bihs[colb + 1] + bhhs[colb + 1];
        float biz0 = bihs[32 + colb] + bhhs[32 + colb], biz1 = bihs[33 + colb] + bhhs[33 + colb];
        float bxn0 = bihs[64 + colb], bxn1 = bihs[65 + colb];
        float bhn0 = bhhs[64 + colb], bhn1 = bhhs[65 + colb];
#pragma unroll
        for (int half = 0; half < 2; half++) {
            int row = wrow + r0 + half * 8;
            int d0 = half * 2, d1 = half * 2 + 1;
            float2 hv = *(const float2*)&hf[row * GHS + colb];
            float rg0 = sigm(ax[0][d0] + ah[0][d0] + bir0);
            float zg0 = sigm(ax[1][d0] + ah[1][d0] + biz0);
            float ng0 = fast_tanh(ax[2][d0] + bxn0 + rg0 * (ah[2][d0] + bhn0));
            float rg1 = sigm(ax[0][d1] + ah[0][d1] + bir1);
            float zg1 = sigm(ax[1][d1] + ah[1][d1] + biz1);
            float ng1 = fast_tanh(ax[2][d1] + bxn1 + rg1 * (ah[2][d1] + bhn1));
            float2 o;
            o.x = (1.f - zg0) * ng0 + zg0 * hv.x;
            o.y = (1.f - zg1) * ng1 + zg1 * hv.y;
            size_t oo = (size_t)(row0 + row) * 32 + colb;
            *(float2*)&dst[oo] = o;
            __half2 oh = __floats2half2_rn(o.x, o.y);   // keep fp16 mirror current for next msg
            *(uint32_t*)(d_h16 + oo) = *(uint32_t*)&oh;
        }
    }
}

// ---------------- launch ----------------
extern "C" void kernel_launch(void* const* d_in, const int* in_sizes, int n_in,
                              void* d_out, int out_size) {
    const float* x     = (const float*)d_in[0];
    const float* er    = (const float*)d_in[1];
    const float* pw1   = (const float*)d_in[2];
    const float* pb1   = (const float*)d_in[3];
    const float* pw2   = (const float*)d_in[4];
    const float* pb2   = (const float*)d_in[5];
    const float* ew1   = (const float*)d_in[6];
    const float* eb1   = (const float*)d_in[7];
    const float* ew2   = (const float*)d_in[8];
    const float* eb2   = (const float*)d_in[9];
    const float* convb = (const float*)d_in[10];
    const float* wih   = (const float*)d_in[11];
    const float* whh   = (const float*)d_in[12];
    const float* bih   = (const float*)d_in[13];
    const float* bhh   = (const float*)d_in[14];
    const int*   esrc  = (const int*)d_in[15];
    const int*   edst  = (const int*)d_in[16];
    float* outp = (float*)d_out;

    cudaFuncSetAttribute(msg_fused, cudaFuncAttributeMaxDynamicSharedMemorySize, SM_TOTAL);
    cudaFuncSetAttribute(gru_kernel, cudaFuncAttributeMaxDynamicSharedMemorySize, G_TOTAL);

    prep_kernel<<<G_BLOCKS + BP_BLOCKS + WP_BLOCKS + H0_BLOCKS, 256>>>(
        er, ew1, eb1, ew2, eb2, wih, whh, x, pw1, pb1, pw2, pb2);
    for (int s = 0; s < 3; s++) {
        msg_fused<<<NTILES, 512, SM_TOTAL>>>(esrc, edst);
        gru_kernel<<<NROWS / 128, 256, G_TOTAL>>>(convb, bih, bhh, outp, s == 2 ? 1 : 0);
    }
}